// round 1
// baseline (speedup 1.0000x reference)
#include <cuda_runtime.h>
#include <math.h>

// Problem constants
#define SS   128          // sequence length S
#define NB   256          // batch N
#define DD   256          // model dim D
#define NH   8            // heads
#define DHD  32           // head dim
#define FFD  1024         // feed-forward dim
#define SN   (SS*NB)      // 32768 rows

// ---------------- scratch (device globals; no runtime allocation) ----------
__device__ float HBUF [SN*DD];        // h (S,N,D)
__device__ float QKVB [SN*3*DD];      // qkv; later reused: nodes | gk | gv
__device__ float BUF1 [SN*FFD];       // ff intermediate / attn out; later: pkW | qgp | qgf
__device__ float BUF2 [SN*DD];        // proj/ff2 out; later: pk
__device__ float GRAPHB[NB*DD];
__device__ float QGGB [NB*DD];
__device__ float WCTB [DD*DD];        // (g_wo @ p_wq / 16)^T
__device__ float BBV  [DD];           // (g_bo @ p_wq)/16
__device__ float QGV2 [DD];           // v2 @ g_wq[256:512]
__device__ float QGFV1[DD];           // v1 @ g_wq[512:768]
__device__ float PKBB [SN];           // pk . BBV per (n,s)

// ---------------- simple copy ------------------------------------------------
__global__ void copy_f4(const float4* __restrict__ src, float4* __restrict__ dst, int n4) {
    int i = blockIdx.x * blockDim.x + threadIdx.x;
    if (i < n4) dst[i] = src[i];
}

// ---------------- fp32 SGEMM: C = A(MxK) @ B(KxNc) + bias, optional ReLU -----
// 128x128 tile, BK=16, 256 threads, 8x8 per thread.
template <int ACT>
__global__ __launch_bounds__(256) void sgemm128(
    const float* __restrict__ A, const float* __restrict__ B,
    const float* __restrict__ bias, float* __restrict__ C,
    int M, int Nc, int K)
{
    __shared__ float As[16][128];
    __shared__ float Bs[16][128];
    int tid = threadIdx.x;
    int bn = blockIdx.x, bm = blockIdx.y;
    int tr = tid >> 4;       // 0..15 -> rows tr*8
    int tc = tid & 15;       // 0..15 -> cols tc*8
    const float* Ab = A + (size_t)bm * 128 * K;
    const float* Bb = B + bn * 128;

    float acc[8][8];
#pragma unroll
    for (int i = 0; i < 8; i++)
#pragma unroll
        for (int j = 0; j < 8; j++) acc[i][j] = 0.f;

    for (int k0 = 0; k0 < K; k0 += 16) {
        // load A 128x16 (512 float4, 2/thread), store transposed
#pragma unroll
        for (int i = 0; i < 2; i++) {
            int li = tid + i * 256;
            int r = li >> 2, c4 = li & 3;
            float4 a = *(const float4*)(Ab + (size_t)r * K + k0 + c4 * 4);
            As[c4 * 4 + 0][r] = a.x;
            As[c4 * 4 + 1][r] = a.y;
            As[c4 * 4 + 2][r] = a.z;
            As[c4 * 4 + 3][r] = a.w;
        }
        // load B 16x128 (512 float4, 2/thread)
#pragma unroll
        for (int i = 0; i < 2; i++) {
            int li = tid + i * 256;
            int r = li >> 5, c4 = li & 31;
            float4 b = *(const float4*)(Bb + (size_t)(k0 + r) * Nc + c4 * 4);
            *(float4*)&Bs[r][c4 * 4] = b;
        }
        __syncthreads();
#pragma unroll
        for (int kk = 0; kk < 16; kk++) {
            float a[8], b[8];
            *(float4*)&a[0] = *(const float4*)&As[kk][tr * 8];
            *(float4*)&a[4] = *(const float4*)&As[kk][tr * 8 + 4];
            *(float4*)&b[0] = *(const float4*)&Bs[kk][tc * 8];
            *(float4*)&b[4] = *(const float4*)&Bs[kk][tc * 8 + 4];
#pragma unroll
            for (int i = 0; i < 8; i++)
#pragma unroll
                for (int j = 0; j < 8; j++) acc[i][j] += a[i] * b[j];
        }
        __syncthreads();
    }

    int col0 = bn * 128 + tc * 8;
    float bv[8];
#pragma unroll
    for (int j = 0; j < 8; j++) bv[j] = bias ? bias[col0 + j] : 0.f;
#pragma unroll
    for (int i = 0; i < 8; i++) {
        int row = bm * 128 + tr * 8 + i;
        float* cp = C + (size_t)row * Nc + col0;
        float o[8];
#pragma unroll
        for (int j = 0; j < 8; j++) {
            float v = acc[i][j] + bv[j];
            if (ACT) v = fmaxf(v, 0.f);
            o[j] = v;
        }
        *(float4*)cp       = make_float4(o[0], o[1], o[2], o[3]);
        *(float4*)(cp + 4) = make_float4(o[4], o[5], o[6], o[7]);
    }
}

// ---------------- encoder attention: one block per (n,h), flash-style --------
__global__ __launch_bounds__(128) void enc_attn_kernel(
    const float* __restrict__ qkv, const int* __restrict__ mask,
    float* __restrict__ outp)
{
    int n = blockIdx.x, h = blockIdx.y, q = threadIdx.x;
    __shared__ float Ks[128][32];
    __shared__ float Vs[128][32];
    __shared__ int   msk[128];

    const float* kr = qkv + ((size_t)q * NB + n) * 768 + 256 + h * 32;
#pragma unroll
    for (int i = 0; i < 8; i++) {
        *(float4*)&Ks[q][i * 4] = *(const float4*)(kr + i * 4);
        *(float4*)&Vs[q][i * 4] = *(const float4*)(kr + 256 + i * 4);
    }
    msk[q] = mask[n * SS + q];

    float qv[32];
    const float* qr = qkv + ((size_t)q * NB + n) * 768 + h * 32;
#pragma unroll
    for (int i = 0; i < 8; i++) *(float4*)&qv[i * 4] = *(const float4*)(qr + i * 4);
    __syncthreads();

    float m = -INFINITY, l = 0.f, acc[32];
#pragma unroll
    for (int j = 0; j < 32; j++) acc[j] = 0.f;

    for (int s = 0; s < 128; s++) {
        float sc;
        if (msk[s] == 0) sc = -1e9f;
        else {
            float d = 0.f;
#pragma unroll
            for (int j = 0; j < 32; j++) d += qv[j] * Ks[s][j];
            sc = d * 0.17677669529663687f;   // 1/sqrt(32)
        }
        float nm   = fmaxf(m, sc);
        float corr = expf(m - nm);
        float p    = expf(sc - nm);
        l = l * corr + p;
#pragma unroll
        for (int j = 0; j < 32; j++) acc[j] = acc[j] * corr + p * Vs[s][j];
        m = nm;
    }
    float inv = 1.f / l;
    float* op = outp + ((size_t)q * NB + n) * DD + h * 32;
#pragma unroll
    for (int j = 0; j < 32; j++) op[j] = acc[j] * inv;
}

// ---------------- residual + LayerNorm (in place into h) --------------------
__global__ __launch_bounds__(256) void ln_res_kernel(
    float* __restrict__ h, const float* __restrict__ r,
    const float* __restrict__ sg, const float* __restrict__ bg)
{
    int row = blockIdx.x, d = threadIdx.x;
    size_t off = (size_t)row * DD + d;
    float v = h[off] + r[off];
    __shared__ float red[8];

    float t = v;
#pragma unroll
    for (int o = 16; o; o >>= 1) t += __shfl_xor_sync(0xffffffffu, t, o);
    if ((d & 31) == 0) red[d >> 5] = t;
    __syncthreads();
    float mu = (red[0] + red[1] + red[2] + red[3] + red[4] + red[5] + red[6] + red[7]) * (1.f / DD);
    __syncthreads();

    float dv = v - mu;
    t = dv * dv;
#pragma unroll
    for (int o = 16; o; o >>= 1) t += __shfl_xor_sync(0xffffffffu, t, o);
    if ((d & 31) == 0) red[d >> 5] = t;
    __syncthreads();
    float var = (red[0] + red[1] + red[2] + red[3] + red[4] + red[5] + red[6] + red[7]) * (1.f / DD);

    h[off] = dv * rsqrtf(var + 1e-5f) * sg[d] + bg[d];
}

// ---------------- transpose h(S,N,D) -> nodes(N,S,D) ------------------------
__global__ void transpose_kernel(const float* __restrict__ h, float* __restrict__ nodes) {
    int b = blockIdx.x;                  // b = n*S + s
    int n = b >> 7, s = b & 127;
    int d = threadIdx.x;
    nodes[(size_t)b * DD + d] = h[((size_t)s * NB + n) * DD + d];
}

// ---------------- graph = mean over s of h ----------------------------------
__global__ void graph_kernel(const float* __restrict__ h, float* __restrict__ g) {
    int n = blockIdx.x, d = threadIdx.x;
    float acc = 0.f;
    for (int s = 0; s < SS; s++) acc += h[((size_t)s * NB + n) * DD + d];
    g[n * DD + d] = acc * (1.f / SS);
}

// ---------------- small precomputes -----------------------------------------
// WCT[j][i] = (g_wo @ p_wq)[i][j] / 16  (so pkW = pk @ WCT)
__global__ void wct_kernel(const float* __restrict__ g_wo, const float* __restrict__ p_wq,
                           float* __restrict__ wct) {
    int j = blockIdx.x, i = threadIdx.x;
    float acc = 0.f;
    for (int k = 0; k < 256; k++) acc += g_wo[i * 256 + k] * p_wq[k * 256 + j];
    wct[j * 256 + i] = acc * 0.0625f;
}
// BB[j] = (g_bo @ p_wq)[j] / 16
__global__ void bb_kernel(const float* __restrict__ g_bo, const float* __restrict__ p_wq,
                          float* __restrict__ bb) {
    int j = threadIdx.x;
    float acc = 0.f;
    for (int i = 0; i < 256; i++) acc += g_bo[i] * p_wq[i * 256 + j];
    bb[j] = acc * 0.0625f;
}
// qg contributions of the fixed v1/v2 context pieces
__global__ void smallprec_kernel(const float* __restrict__ g_wq,
                                 const float* __restrict__ v1, const float* __restrict__ v2,
                                 float* __restrict__ qgv2, float* __restrict__ qgfv1) {
    int j = threadIdx.x;
    float a = 0.f, b = 0.f;
    for (int k = 0; k < 256; k++) {
        a += v2[k] * g_wq[(256 + k) * 256 + j];
        b += v1[k] * g_wq[(512 + k) * 256 + j];
    }
    qgv2[j] = a;
    qgfv1[j] = b;
}
// PKB[row] = pk[row] . BB   (one warp per row, 8 rows/block)
__global__ __launch_bounds__(256) void pkb_kernel(const float* __restrict__ pk,
                                                  const float* __restrict__ bb,
                                                  float* __restrict__ pkb) {
    int w = threadIdx.x >> 5, lane = threadIdx.x & 31;
    int row = blockIdx.x * 8 + w;
    const float* p = pk + (size_t)row * 256;
    float acc = 0.f;
#pragma unroll
    for (int k = 0; k < 8; k++) acc += p[lane + k * 32] * bb[lane + k * 32];
#pragma unroll
    for (int o = 16; o; o >>= 1) acc += __shfl_xor_sync(0xffffffffu, acc, o);
    if (!lane) pkb[row] = acc;
}

// ---------------- the whole 128-step greedy decode: 1 block per n -----------
__global__ __launch_bounds__(256) void decode_kernel(
    const int*   __restrict__ mask,
    const float* __restrict__ gk,  const float* __restrict__ gv,
    const float* __restrict__ pkw, const float* __restrict__ qgp,
    const float* __restrict__ qgf, const float* __restrict__ qgg,
    const float* __restrict__ qgv2, const float* __restrict__ qgfv1,
    const float* __restrict__ pkb, float* __restrict__ out)
{
    int n = blockIdx.x;
    int tid = threadIdx.x;
    __shared__ float qg[256], glp[256], qgPrev[256], qgFirst[256];
    __shared__ float att[8][128];
    __shared__ float logits[128];
    __shared__ unsigned mbits[4];
    __shared__ int cur;

    qgPrev[tid]  = qgv2[tid];
    qgFirst[tid] = qgfv1[tid];
    if (tid < 4) {
        unsigned b = 0;
        for (int j = 0; j < 32; j++)
            if (mask[n * SS + tid * 32 + j] == 0) b |= (1u << j);
        mbits[tid] = b;
    }
    float lps = 0.f;
    const float* qggn = qgg + n * 256;
    size_t nbase = (size_t)n * SS * DD;
    __syncthreads();

    for (int t = 0; t < SS; t++) {
        qg[tid] = qggn[tid] + qgPrev[tid] + qgFirst[tid];
        __syncthreads();

        // scores: 1024 (h,s) entries, 4 per thread
#pragma unroll
        for (int i = 0; i < 4; i++) {
            int idx = tid + i * 256;
            int h = idx >> 7, s = idx & 127;
            float v;
            if ((mbits[s >> 5] >> (s & 31)) & 1u) v = -1e9f;
            else {
                const float4* g  = (const float4*)(gk + nbase + (size_t)s * DD + h * 32);
                const float4* qp = (const float4*)(qg + h * 32);
                float acc = 0.f;
#pragma unroll
                for (int j = 0; j < 8; j++) {
                    float4 a = g[j], b = qp[j];
                    acc += a.x * b.x + a.y * b.y + a.z * b.z + a.w * b.w;
                }
                v = acc * 0.17677669529663687f;
            }
            att[h][s] = v;
        }
        __syncthreads();

        // softmax per head: warp w handles head w
        {
            int w = tid >> 5, lane = tid & 31;
            float v0 = att[w][lane], v1 = att[w][lane + 32],
                  v2 = att[w][lane + 64], v3 = att[w][lane + 96];
            float m = fmaxf(fmaxf(v0, v1), fmaxf(v2, v3));
#pragma unroll
            for (int o = 16; o; o >>= 1) m = fmaxf(m, __shfl_xor_sync(0xffffffffu, m, o));
            float e0 = expf(v0 - m), e1 = expf(v1 - m), e2 = expf(v2 - m), e3 = expf(v3 - m);
            float s = e0 + e1 + e2 + e3;
#pragma unroll
            for (int o = 16; o; o >>= 1) s += __shfl_xor_sync(0xffffffffu, s, o);
            float inv = 1.f / s;
            att[w][lane]      = e0 * inv;
            att[w][lane + 32] = e1 * inv;
            att[w][lane + 64] = e2 * inv;
            att[w][lane + 96] = e3 * inv;
        }
        __syncthreads();

        // glp[d] = sum_s att[h(d)][s] * gv[n,s,d]   (coalesced over d)
        {
            int h = tid >> 5;
            float acc = 0.f;
            const float* gvb = gv + nbase + tid;
#pragma unroll 4
            for (int s = 0; s < 128; s++) acc += att[h][s] * gvb[(size_t)s * DD];
            glp[tid] = acc;
        }
        __syncthreads();

        // logits[s] = 10*tanh(glp . pkW[n,s] + pkb[n,s]); 2 threads per s
        {
            int s = tid >> 1, half = tid & 1;
            const float4* p  = (const float4*)(pkw + nbase + (size_t)s * DD + half * 128);
            const float4* gp = (const float4*)(glp + half * 128);
            float acc = 0.f;
#pragma unroll
            for (int j = 0; j < 32; j++) {
                float4 a = p[j], b = gp[j];
                acc += a.x * b.x + a.y * b.y + a.z * b.z + a.w * b.w;
            }
            acc += __shfl_xor_sync(0xffffffffu, acc, 1);
            if (!half) {
                float lg;
                if ((mbits[s >> 5] >> (s & 31)) & 1u) lg = -1e9f;
                else lg = 10.f * tanhf(acc + pkb[n * SS + s]);
                logits[s] = lg;
            }
        }
        __syncthreads();

        // argmax (first-max tie-break) + logsumexp in warp 0
        if (tid < 32) {
            float v[4];
#pragma unroll
            for (int k = 0; k < 4; k++) v[k] = logits[tid + k * 32];
            float bvv = v[0]; int bi = tid;
#pragma unroll
            for (int k = 1; k < 4; k++) {
                int s = tid + k * 32;
                if (v[k] > bvv) { bvv = v[k]; bi = s; }
            }
#pragma unroll
            for (int o = 16; o; o >>= 1) {
                float ov = __shfl_xor_sync(0xffffffffu, bvv, o);
                int   oi = __shfl_xor_sync(0xffffffffu, bi, o);
                if (ov > bvv || (ov == bvv && oi < bi)) { bvv = ov; bi = oi; }
            }
            float ssum = 0.f;
#pragma unroll
            for (int k = 0; k < 4; k++) ssum += expf(v[k] - bvv);
#pragma unroll
            for (int o = 16; o; o >>= 1) ssum += __shfl_xor_sync(0xffffffffu, ssum, o);
            if (tid == 0) { lps += -logf(ssum); cur = bi; }
        }
        __syncthreads();

        int ci = cur;
        qgPrev[tid] = qgp[nbase + (size_t)ci * DD + tid];
        if (t == 0) qgFirst[tid] = qgf[nbase + (size_t)ci * DD + tid];
        if (tid == 0) mbits[ci >> 5] |= (1u << (ci & 31));
        __syncthreads();
    }
    if (tid == 0) out[n] = lps;
}

// ---------------- driver ------------------------------------------------------
extern "C" void kernel_launch(void* const* d_in, const int* in_sizes, int n_in,
                              void* d_out, int out_size)
{
    (void)in_sizes; (void)n_in; (void)out_size;
    const float* x        = (const float*)d_in[0];
    const int*   mask     = (const int*)  d_in[1];
    const float* qkv_w    = (const float*)d_in[2];
    const float* qkv_b    = (const float*)d_in[3];
    const float* out_w    = (const float*)d_in[4];
    const float* out_b    = (const float*)d_in[5];
    const float* ff1_w    = (const float*)d_in[6];
    const float* ff1_b    = (const float*)d_in[7];
    const float* ff2_w    = (const float*)d_in[8];
    const float* ff2_b    = (const float*)d_in[9];
    const float* ln1_s    = (const float*)d_in[10];
    const float* ln1_b    = (const float*)d_in[11];
    const float* ln2_s    = (const float*)d_in[12];
    const float* ln2_b    = (const float*)d_in[13];
    const float* v1       = (const float*)d_in[14];
    const float* v2       = (const float*)d_in[15];
    const float* g_wq     = (const float*)d_in[16];
    const float* g_wk     = (const float*)d_in[17];
    const float* g_wv     = (const float*)d_in[18];
    const float* g_wo     = (const float*)d_in[19];
    const float* g_bo     = (const float*)d_in[20];
    const float* p_wq     = (const float*)d_in[21];
    const float* p_wk     = (const float*)d_in[22];
    float* out = (float*)d_out;

    float *hbuf, *qkvb, *buf1, *buf2, *graphb, *qggb, *wctb, *bbv, *qgv2, *qgfv1, *pkbb;
    cudaGetSymbolAddress((void**)&hbuf,  HBUF);
    cudaGetSymbolAddress((void**)&qkvb,  QKVB);
    cudaGetSymbolAddress((void**)&buf1,  BUF1);
    cudaGetSymbolAddress((void**)&buf2,  BUF2);
    cudaGetSymbolAddress((void**)&graphb,GRAPHB);
    cudaGetSymbolAddress((void**)&qggb,  QGGB);
    cudaGetSymbolAddress((void**)&wctb,  WCTB);
    cudaGetSymbolAddress((void**)&bbv,   BBV);
    cudaGetSymbolAddress((void**)&qgv2,  QGV2);
    cudaGetSymbolAddress((void**)&qgfv1, QGFV1);
    cudaGetSymbolAddress((void**)&pkbb,  PKBB);

    // h = x
    copy_f4<<<(SN * DD / 4 + 255) / 256, 256>>>((const float4*)x, (float4*)hbuf, SN * DD / 4);

    // ---- encoder: 3 layers ----
    for (int i = 0; i < 3; i++) {
        sgemm128<0><<<dim3(6, 256), 256>>>(hbuf, qkv_w + (size_t)i * DD * 3 * DD,
                                           qkv_b + i * 3 * DD, qkvb, SN, 768, DD);
        enc_attn_kernel<<<dim3(NB, NH), 128>>>(qkvb, mask, buf1);
        sgemm128<0><<<dim3(2, 256), 256>>>(buf1, out_w + (size_t)i * DD * DD,
                                           out_b + i * DD, buf2, SN, DD, DD);
        ln_res_kernel<<<SN, 256>>>(hbuf, buf2, ln1_s + i * DD, ln1_b + i * DD);
        sgemm128<1><<<dim3(8, 256), 256>>>(hbuf, ff1_w + (size_t)i * DD * FFD,
                                           ff1_b + i * FFD, buf1, SN, FFD, DD);
        sgemm128<0><<<dim3(2, 256), 256>>>(buf1, ff2_w + (size_t)i * FFD * DD,
                                           ff2_b + i * DD, buf2, SN, DD, FFD);
        ln_res_kernel<<<SN, 256>>>(hbuf, buf2, ln2_s + i * DD, ln2_b + i * DD);
    }

    // ---- decode precompute ----
    float* nodes = qkvb;                       // (N,S,D)
    float* gk    = qkvb + (size_t)SN * DD;
    float* gv    = qkvb + 2 * (size_t)SN * DD;
    float* pkw   = buf1;
    float* qgp   = buf1 + (size_t)SN * DD;
    float* qgf   = buf1 + 2 * (size_t)SN * DD;
    float* pk    = buf2;

    transpose_kernel<<<SN, 256>>>(hbuf, nodes);
    graph_kernel<<<NB, 256>>>(hbuf, graphb);

    sgemm128<0><<<dim3(2, 256), 256>>>(nodes, g_wk, nullptr, gk, SN, DD, DD);
    sgemm128<0><<<dim3(2, 256), 256>>>(nodes, g_wv, nullptr, gv, SN, DD, DD);
    sgemm128<0><<<dim3(2, 256), 256>>>(nodes, p_wk, nullptr, pk, SN, DD, DD);

    wct_kernel<<<256, 256>>>(g_wo, p_wq, wctb);
    bb_kernel<<<1, 256>>>(g_bo, p_wq, bbv);
    smallprec_kernel<<<1, 256>>>(g_wq, v1, v2, qgv2, qgfv1);

    sgemm128<0><<<dim3(2, 256), 256>>>(pk, wctb, nullptr, pkw, SN, DD, DD);
    pkb_kernel<<<SN / 8, 256>>>(pk, bbv, pkbb);

    sgemm128<0><<<dim3(2, 2), 256>>>(graphb, g_wq, nullptr, qggb, NB, DD, DD);
    sgemm128<0><<<dim3(2, 256), 256>>>(nodes, g_wq + 256 * 256, nullptr, qgp, SN, DD, DD);
    sgemm128<0><<<dim3(2, 256), 256>>>(nodes, g_wq + 512 * 256, nullptr, qgf, SN, DD, DD);

    // ---- full greedy decode in one kernel ----
    decode_kernel<<<NB, 256>>>(mask, gk, gv, pkw, qgp, qgf, qggb,
                               qgv2, qgfv1, pkbb, out);
}

// round 2
// speedup vs baseline: 1.5583x; 1.5583x over previous
#include <cuda_runtime.h>
#include <math.h>

// Problem constants
#define SS   128          // sequence length S
#define NB   256          // batch N
#define DD   256          // model dim D
#define NH   8            // heads
#define DHD  32           // head dim
#define FFD  1024         // feed-forward dim
#define SN   (SS*NB)      // 32768 rows

// ---------------- scratch (device globals; no runtime allocation) ----------
__device__ float HBUF [SN*DD];        // h (S,N,D)
__device__ float QKVB [SN*3*DD];      // qkv; later reused: nodes | gk | gv
__device__ float BUF1 [SN*FFD];       // ff intermediate / attn out; later: pkW | qgp | qgf
__device__ float BUF2 [SN*DD];        // proj/ff2 out; later: pk
__device__ float GRAPHB[NB*DD];
__device__ float QGGB [NB*DD];
__device__ float WCTB [DD*DD];        // (g_wo @ p_wq / 16)^T
__device__ float BBV  [DD];           // (g_bo @ p_wq)/16
__device__ float QGV2 [DD];           // v2 @ g_wq[256:512]
__device__ float QGFV1[DD];           // v1 @ g_wq[512:768]
__device__ float PKBB [SN];           // pk . BBV per (n,s)

// ---------------- simple copy ------------------------------------------------
__global__ void copy_f4(const float4* __restrict__ src, float4* __restrict__ dst, int n4) {
    int i = blockIdx.x * blockDim.x + threadIdx.x;
    if (i < n4) dst[i] = src[i];
}

// ---------------- tf32 helpers ----------------------------------------------
__device__ __forceinline__ unsigned f2tf(float x) {
    unsigned u;
    asm("cvt.rna.tf32.f32 %0, %1;" : "=r"(u) : "f"(x));
    return u;
}
__device__ __forceinline__ float4 f2tf4(float4 v) {
    float4 o;
    o.x = __uint_as_float(f2tf(v.x));
    o.y = __uint_as_float(f2tf(v.y));
    o.z = __uint_as_float(f2tf(v.z));
    o.w = __uint_as_float(f2tf(v.w));
    return o;
}
__device__ __forceinline__ void mma_tf32(float* d, const unsigned* a, const unsigned* b) {
    asm volatile(
        "mma.sync.aligned.m16n8k8.row.col.f32.tf32.tf32.f32 "
        "{%0,%1,%2,%3},{%4,%5,%6,%7},{%8,%9},{%0,%1,%2,%3};"
        : "+f"(d[0]), "+f"(d[1]), "+f"(d[2]), "+f"(d[3])
        : "r"(a[0]), "r"(a[1]), "r"(a[2]), "r"(a[3]), "r"(b[0]), "r"(b[1]));
}

// ---------------- tensor-core GEMM: C = A(MxK) @ B(KxNc) + bias, opt ReLU ----
// 128x128 tile, BK=16, 256 threads (8 warps), warp tile 64x32 via m16n8k8 tf32.
template <int ACT>
__global__ __launch_bounds__(256) void sgemm_tc(
    const float* __restrict__ A, const float* __restrict__ B,
    const float* __restrict__ bias, float* __restrict__ C,
    int M, int Nc, int K)
{
    __shared__ float As[128][20];   // [m][k], pad 20 -> conflict-free frag loads
    __shared__ float Bs[16][136];   // [k][n], pad 136 -> conflict-free frag loads
    int tid  = threadIdx.x;
    int lane = tid & 31, wid = tid >> 5;
    int wm = wid >> 2, wn = wid & 3;          // warp tile: (wm*64, wn*32)
    const float* Ab = A + (size_t)blockIdx.y * 128 * K;
    const float* Bb = B + blockIdx.x * 128;

    float acc[4][4][4];
#pragma unroll
    for (int i = 0; i < 4; i++)
#pragma unroll
        for (int j = 0; j < 4; j++)
#pragma unroll
            for (int r = 0; r < 4; r++) acc[i][j][r] = 0.f;

    for (int k0 = 0; k0 < K; k0 += 16) {
        // A tile 128x16 -> As[m][k]  (512 float4, 2/thread)
#pragma unroll
        for (int i = 0; i < 2; i++) {
            int li = tid + i * 256;
            int r = li >> 2, c4 = li & 3;
            float4 a = *(const float4*)(Ab + (size_t)r * K + k0 + c4 * 4);
            *(float4*)&As[r][c4 * 4] = f2tf4(a);
        }
        // B tile 16x128 -> Bs[k][n]  (512 float4, 2/thread)
#pragma unroll
        for (int i = 0; i < 2; i++) {
            int li = tid + i * 256;
            int r = li >> 5, c4 = li & 31;
            float4 b = *(const float4*)(Bb + (size_t)(k0 + r) * Nc + c4 * 4);
            *(float4*)&Bs[r][c4 * 4] = f2tf4(b);
        }
        __syncthreads();

#pragma unroll
        for (int kk = 0; kk < 16; kk += 8) {
            unsigned afr[4][4], bfr[4][2];
            int ar = wm * 64 + (lane >> 2);
            int ac = kk + (lane & 3);
#pragma unroll
            for (int mt = 0; mt < 4; mt++) {
                afr[mt][0] = __float_as_uint(As[ar + mt * 16    ][ac    ]);
                afr[mt][1] = __float_as_uint(As[ar + mt * 16 + 8][ac    ]);
                afr[mt][2] = __float_as_uint(As[ar + mt * 16    ][ac + 4]);
                afr[mt][3] = __float_as_uint(As[ar + mt * 16 + 8][ac + 4]);
            }
            int bc = wn * 32 + (lane >> 2);
            int br = kk + (lane & 3);
#pragma unroll
            for (int nt = 0; nt < 4; nt++) {
                bfr[nt][0] = __float_as_uint(Bs[br    ][bc + nt * 8]);
                bfr[nt][1] = __float_as_uint(Bs[br + 4][bc + nt * 8]);
            }
#pragma unroll
            for (int mt = 0; mt < 4; mt++)
#pragma unroll
                for (int nt = 0; nt < 4; nt++)
                    mma_tf32(acc[mt][nt], afr[mt], bfr[nt]);
        }
        __syncthreads();
    }

    // epilogue
    int rbase = blockIdx.y * 128 + wm * 64 + (lane >> 2);
    int cbase = blockIdx.x * 128 + wn * 32 + 2 * (lane & 3);
#pragma unroll
    for (int nt = 0; nt < 4; nt++) {
        int col = cbase + nt * 8;
        float b0 = bias ? bias[col] : 0.f;
        float b1 = bias ? bias[col + 1] : 0.f;
#pragma unroll
        for (int mt = 0; mt < 4; mt++) {
            int row = rbase + mt * 16;
            float v0 = acc[mt][nt][0] + b0;
            float v1 = acc[mt][nt][1] + b1;
            float v2 = acc[mt][nt][2] + b0;
            float v3 = acc[mt][nt][3] + b1;
            if (ACT) {
                v0 = fmaxf(v0, 0.f); v1 = fmaxf(v1, 0.f);
                v2 = fmaxf(v2, 0.f); v3 = fmaxf(v3, 0.f);
            }
            *(float2*)(C + (size_t)row * Nc + col)       = make_float2(v0, v1);
            *(float2*)(C + (size_t)(row + 8) * Nc + col) = make_float2(v2, v3);
        }
    }
}

// ---------------- encoder attention: one block per (n,h), flash-style --------
__global__ __launch_bounds__(128) void enc_attn_kernel(
    const float* __restrict__ qkv, const int* __restrict__ mask,
    float* __restrict__ outp)
{
    int n = blockIdx.x, h = blockIdx.y, q = threadIdx.x;
    __shared__ float Ks[128][32];
    __shared__ float Vs[128][32];
    __shared__ int   msk[128];

    const float* kr = qkv + ((size_t)q * NB + n) * 768 + 256 + h * 32;
#pragma unroll
    for (int i = 0; i < 8; i++) {
        *(float4*)&Ks[q][i * 4] = *(const float4*)(kr + i * 4);
        *(float4*)&Vs[q][i * 4] = *(const float4*)(kr + 256 + i * 4);
    }
    msk[q] = mask[n * SS + q];

    float qv[32];
    const float* qr = qkv + ((size_t)q * NB + n) * 768 + h * 32;
#pragma unroll
    for (int i = 0; i < 8; i++) *(float4*)&qv[i * 4] = *(const float4*)(qr + i * 4);
    __syncthreads();

    float m = -INFINITY, l = 0.f, acc[32];
#pragma unroll
    for (int j = 0; j < 32; j++) acc[j] = 0.f;

    for (int s = 0; s < 128; s++) {
        float sc;
        if (msk[s] == 0) sc = -1e9f;
        else {
            float d = 0.f;
#pragma unroll
            for (int j = 0; j < 32; j++) d += qv[j] * Ks[s][j];
            sc = d * 0.17677669529663687f;   // 1/sqrt(32)
        }
        float nm   = fmaxf(m, sc);
        float corr = expf(m - nm);
        float p    = expf(sc - nm);
        l = l * corr + p;
#pragma unroll
        for (int j = 0; j < 32; j++) acc[j] = acc[j] * corr + p * Vs[s][j];
        m = nm;
    }
    float inv = 1.f / l;
    float* op = outp + ((size_t)q * NB + n) * DD + h * 32;
#pragma unroll
    for (int j = 0; j < 32; j++) op[j] = acc[j] * inv;
}

// ---------------- residual + LayerNorm (in place into h) --------------------
__global__ __launch_bounds__(256) void ln_res_kernel(
    float* __restrict__ h, const float* __restrict__ r,
    const float* __restrict__ sg, const float* __restrict__ bg)
{
    int row = blockIdx.x, d = threadIdx.x;
    size_t off = (size_t)row * DD + d;
    float v = h[off] + r[off];
    __shared__ float red[8];

    float t = v;
#pragma unroll
    for (int o = 16; o; o >>= 1) t += __shfl_xor_sync(0xffffffffu, t, o);
    if ((d & 31) == 0) red[d >> 5] = t;
    __syncthreads();
    float mu = (red[0] + red[1] + red[2] + red[3] + red[4] + red[5] + red[6] + red[7]) * (1.f / DD);
    __syncthreads();

    float dv = v - mu;
    t = dv * dv;
#pragma unroll
    for (int o = 16; o; o >>= 1) t += __shfl_xor_sync(0xffffffffu, t, o);
    if ((d & 31) == 0) red[d >> 5] = t;
    __syncthreads();
    float var = (red[0] + red[1] + red[2] + red[3] + red[4] + red[5] + red[6] + red[7]) * (1.f / DD);

    h[off] = dv * rsqrtf(var + 1e-5f) * sg[d] + bg[d];
}

// ---------------- transpose h(S,N,D) -> nodes(N,S,D) ------------------------
__global__ void transpose_kernel(const float* __restrict__ h, float* __restrict__ nodes) {
    int b = blockIdx.x;                  // b = n*S + s
    int n = b >> 7, s = b & 127;
    int d = threadIdx.x;
    nodes[(size_t)b * DD + d] = h[((size_t)s * NB + n) * DD + d];
}

// ---------------- graph = mean over s of h ----------------------------------
__global__ void graph_kernel(const float* __restrict__ h, float* __restrict__ g) {
    int n = blockIdx.x, d = threadIdx.x;
    float acc = 0.f;
    for (int s = 0; s < SS; s++) acc += h[((size_t)s * NB + n) * DD + d];
    g[n * DD + d] = acc * (1.f / SS);
}

// ---------------- small precomputes -----------------------------------------
// WCT[j][i] = (g_wo @ p_wq)[i][j] / 16  (so pkW = pk @ WCT)
__global__ void wct_kernel(const float* __restrict__ g_wo, const float* __restrict__ p_wq,
                           float* __restrict__ wct) {
    int j = blockIdx.x, i = threadIdx.x;
    float acc = 0.f;
    for (int k = 0; k < 256; k++) acc += g_wo[i * 256 + k] * p_wq[k * 256 + j];
    wct[j * 256 + i] = acc * 0.0625f;
}
// BB[j] = (g_bo @ p_wq)[j] / 16
__global__ void bb_kernel(const float* __restrict__ g_bo, const float* __restrict__ p_wq,
                          float* __restrict__ bb) {
    int j = threadIdx.x;
    float acc = 0.f;
    for (int i = 0; i < 256; i++) acc += g_bo[i] * p_wq[i * 256 + j];
    bb[j] = acc * 0.0625f;
}
// qg contributions of the fixed v1/v2 context pieces
__global__ void smallprec_kernel(const float* __restrict__ g_wq,
                                 const float* __restrict__ v1, const float* __restrict__ v2,
                                 float* __restrict__ qgv2, float* __restrict__ qgfv1) {
    int j = threadIdx.x;
    float a = 0.f, b = 0.f;
    for (int k = 0; k < 256; k++) {
        a += v2[k] * g_wq[(256 + k) * 256 + j];
        b += v1[k] * g_wq[(512 + k) * 256 + j];
    }
    qgv2[j] = a;
    qgfv1[j] = b;
}
// PKB[row] = pk[row] . BB   (one warp per row, 8 rows/block)
__global__ __launch_bounds__(256) void pkb_kernel(const float* __restrict__ pk,
                                                  const float* __restrict__ bb,
                                                  float* __restrict__ pkb) {
    int w = threadIdx.x >> 5, lane = threadIdx.x & 31;
    int row = blockIdx.x * 8 + w;
    const float* p = pk + (size_t)row * 256;
    float acc = 0.f;
#pragma unroll
    for (int k = 0; k < 8; k++) acc += p[lane + k * 32] * bb[lane + k * 32];
#pragma unroll
    for (int o = 16; o; o >>= 1) acc += __shfl_xor_sync(0xffffffffu, acc, o);
    if (!lane) pkb[row] = acc;
}

// ---------------- the whole 128-step greedy decode: 1 block per n -----------
__global__ __launch_bounds__(256) void decode_kernel(
    const int*   __restrict__ mask,
    const float* __restrict__ gk,  const float* __restrict__ gv,
    const float* __restrict__ pkw, const float* __restrict__ qgp,
    const float* __restrict__ qgf, const float* __restrict__ qgg,
    const float* __restrict__ qgv2, const float* __restrict__ qgfv1,
    const float* __restrict__ pkb, float* __restrict__ out)
{
    int n = blockIdx.x;
    int tid = threadIdx.x;
    __shared__ float qg[256], glp[256], qgPrev[256], qgFirst[256];
    __shared__ float att[8][128];
    __shared__ float logits[128];
    __shared__ unsigned mbits[4];
    __shared__ int cur;

    qgPrev[tid]  = qgv2[tid];
    qgFirst[tid] = qgfv1[tid];
    if (tid < 4) {
        unsigned b = 0;
        for (int j = 0; j < 32; j++)
            if (mask[n * SS + tid * 32 + j] == 0) b |= (1u << j);
        mbits[tid] = b;
    }
    float lps = 0.f;
    const float* qggn = qgg + n * 256;
    size_t nbase = (size_t)n * SS * DD;
    __syncthreads();

    for (int t = 0; t < SS; t++) {
        qg[tid] = qggn[tid] + qgPrev[tid] + qgFirst[tid];
        __syncthreads();

        // scores: 1024 (h,s) entries, 4 per thread
#pragma unroll
        for (int i = 0; i < 4; i++) {
            int idx = tid + i * 256;
            int h = idx >> 7, s = idx & 127;
            float v;
            if ((mbits[s >> 5] >> (s & 31)) & 1u) v = -1e9f;
            else {
                const float4* g  = (const float4*)(gk + nbase + (size_t)s * DD + h * 32);
                const float4* qp = (const float4*)(qg + h * 32);
                float acc = 0.f;
#pragma unroll
                for (int j = 0; j < 8; j++) {
                    float4 a = g[j], b = qp[j];
                    acc += a.x * b.x + a.y * b.y + a.z * b.z + a.w * b.w;
                }
                v = acc * 0.17677669529663687f;
            }
            att[h][s] = v;
        }
        __syncthreads();

        // softmax per head: warp w handles head w
        {
            int w = tid >> 5, lane = tid & 31;
            float v0 = att[w][lane], v1 = att[w][lane + 32],
                  v2 = att[w][lane + 64], v3 = att[w][lane + 96];
            float m = fmaxf(fmaxf(v0, v1), fmaxf(v2, v3));
#pragma unroll
            for (int o = 16; o; o >>= 1) m = fmaxf(m, __shfl_xor_sync(0xffffffffu, m, o));
            float e0 = expf(v0 - m), e1 = expf(v1 - m), e2 = expf(v2 - m), e3 = expf(v3 - m);
            float s = e0 + e1 + e2 + e3;
#pragma unroll
            for (int o = 16; o; o >>= 1) s += __shfl_xor_sync(0xffffffffu, s, o);
            float inv = 1.f / s;
            att[w][lane]      = e0 * inv;
            att[w][lane + 32] = e1 * inv;
            att[w][lane + 64] = e2 * inv;
            att[w][lane + 96] = e3 * inv;
        }
        __syncthreads();

        // glp[d] = sum_s att[h(d)][s] * gv[n,s,d]   (coalesced over d)
        {
            int h = tid >> 5;
            float acc = 0.f;
            const float* gvb = gv + nbase + tid;
#pragma unroll 4
            for (int s = 0; s < 128; s++) acc += att[h][s] * gvb[(size_t)s * DD];
            glp[tid] = acc;
        }
        __syncthreads();

        // logits[s] = 10*tanh(glp . pkW[n,s] + pkb[n,s]); 2 threads per s
        {
            int s = tid >> 1, half = tid & 1;
            const float4* p  = (const float4*)(pkw + nbase + (size_t)s * DD + half * 128);
            const float4* gp = (const float4*)(glp + half * 128);
            float acc = 0.f;
#pragma unroll
            for (int j = 0; j < 32; j++) {
                float4 a = p[j], b = gp[j];
                acc += a.x * b.x + a.y * b.y + a.z * b.z + a.w * b.w;
            }
            acc += __shfl_xor_sync(0xffffffffu, acc, 1);
            if (!half) {
                float lg;
                if ((mbits[s >> 5] >> (s & 31)) & 1u) lg = -1e9f;
                else lg = 10.f * tanhf(acc + pkb[n * SS + s]);
                logits[s] = lg;
            }
        }
        __syncthreads();

        // argmax (first-max tie-break) + logsumexp in warp 0
        if (tid < 32) {
            float v[4];
#pragma unroll
            for (int k = 0; k < 4; k++) v[k] = logits[tid + k * 32];
            float bvv = v[0]; int bi = tid;
#pragma unroll
            for (int k = 1; k < 4; k++) {
                int s = tid + k * 32;
                if (v[k] > bvv) { bvv = v[k]; bi = s; }
            }
#pragma unroll
            for (int o = 16; o; o >>= 1) {
                float ov = __shfl_xor_sync(0xffffffffu, bvv, o);
                int   oi = __shfl_xor_sync(0xffffffffu, bi, o);
                if (ov > bvv || (ov == bvv && oi < bi)) { bvv = ov; bi = oi; }
            }
            float ssum = 0.f;
#pragma unroll
            for (int k = 0; k < 4; k++) ssum += expf(v[k] - bvv);
#pragma unroll
            for (int o = 16; o; o >>= 1) ssum += __shfl_xor_sync(0xffffffffu, ssum, o);
            if (tid == 0) { lps += -logf(ssum); cur = bi; }
        }
        __syncthreads();

        int ci = cur;
        qgPrev[tid] = qgp[nbase + (size_t)ci * DD + tid];
        if (t == 0) qgFirst[tid] = qgf[nbase + (size_t)ci * DD + tid];
        if (tid == 0) mbits[ci >> 5] |= (1u << (ci & 31));
        __syncthreads();
    }
    if (tid == 0) out[n] = lps;
}

// ---------------- driver ------------------------------------------------------
extern "C" void kernel_launch(void* const* d_in, const int* in_sizes, int n_in,
                              void* d_out, int out_size)
{
    (void)in_sizes; (void)n_in; (void)out_size;
    const float* x        = (const float*)d_in[0];
    const int*   mask     = (const int*)  d_in[1];
    const float* qkv_w    = (const float*)d_in[2];
    const float* qkv_b    = (const float*)d_in[3];
    const float* out_w    = (const float*)d_in[4];
    const float* out_b    = (const float*)d_in[5];
    const float* ff1_w    = (const float*)d_in[6];
    const float* ff1_b    = (const float*)d_in[7];
    const float* ff2_w    = (const float*)d_in[8];
    const float* ff2_b    = (const float*)d_in[9];
    const float* ln1_s    = (const float*)d_in[10];
    const float* ln1_b    = (const float*)d_in[11];
    const float* ln2_s    = (const float*)d_in[12];
    const float* ln2_b    = (const float*)d_in[13];
    const float* v1       = (const float*)d_in[14];
    const float* v2       = (const float*)d_in[15];
    const float* g_wq     = (const float*)d_in[16];
    const float* g_wk     = (const float*)d_in[17];
    const float* g_wv     = (const float*)d_in[18];
    const float* g_wo     = (const float*)d_in[19];
    const float* g_bo     = (const float*)d_in[20];
    const float* p_wq     = (const float*)d_in[21];
    const float* p_wk     = (const float*)d_in[22];
    float* out = (float*)d_out;

    float *hbuf, *qkvb, *buf1, *buf2, *graphb, *qggb, *wctb, *bbv, *qgv2, *qgfv1, *pkbb;
    cudaGetSymbolAddress((void**)&hbuf,  HBUF);
    cudaGetSymbolAddress((void**)&qkvb,  QKVB);
    cudaGetSymbolAddress((void**)&buf1,  BUF1);
    cudaGetSymbolAddress((void**)&buf2,  BUF2);
    cudaGetSymbolAddress((void**)&graphb,GRAPHB);
    cudaGetSymbolAddress((void**)&qggb,  QGGB);
    cudaGetSymbolAddress((void**)&wctb,  WCTB);
    cudaGetSymbolAddress((void**)&bbv,   BBV);
    cudaGetSymbolAddress((void**)&qgv2,  QGV2);
    cudaGetSymbolAddress((void**)&qgfv1, QGFV1);
    cudaGetSymbolAddress((void**)&pkbb,  PKBB);

    // h = x
    copy_f4<<<(SN * DD / 4 + 255) / 256, 256>>>((const float4*)x, (float4*)hbuf, SN * DD / 4);

    // ---- encoder: 3 layers ----
    for (int i = 0; i < 3; i++) {
        sgemm_tc<0><<<dim3(6, 256), 256>>>(hbuf, qkv_w + (size_t)i * DD * 3 * DD,
                                           qkv_b + i * 3 * DD, qkvb, SN, 768, DD);
        enc_attn_kernel<<<dim3(NB, NH), 128>>>(qkvb, mask, buf1);
        sgemm_tc<0><<<dim3(2, 256), 256>>>(buf1, out_w + (size_t)i * DD * DD,
                                           out_b + i * DD, buf2, SN, DD, DD);
        ln_res_kernel<<<SN, 256>>>(hbuf, buf2, ln1_s + i * DD, ln1_b + i * DD);
        sgemm_tc<1><<<dim3(8, 256), 256>>>(hbuf, ff1_w + (size_t)i * DD * FFD,
                                           ff1_b + i * FFD, buf1, SN, FFD, DD);
        sgemm_tc<0><<<dim3(2, 256), 256>>>(buf1, ff2_w + (size_t)i * FFD * DD,
                                           ff2_b + i * DD, buf2, SN, DD, FFD);
        ln_res_kernel<<<SN, 256>>>(hbuf, buf2, ln2_s + i * DD, ln2_b + i * DD);
    }

    // ---- decode precompute ----
    float* nodes = qkvb;                       // (N,S,D)
    float* gk    = qkvb + (size_t)SN * DD;
    float* gv    = qkvb + 2 * (size_t)SN * DD;
    float* pkw   = buf1;
    float* qgp   = buf1 + (size_t)SN * DD;
    float* qgf   = buf1 + 2 * (size_t)SN * DD;
    float* pk    = buf2;

    transpose_kernel<<<SN, 256>>>(hbuf, nodes);
    graph_kernel<<<NB, 256>>>(hbuf, graphb);

    sgemm_tc<0><<<dim3(2, 256), 256>>>(nodes, g_wk, nullptr, gk, SN, DD, DD);
    sgemm_tc<0><<<dim3(2, 256), 256>>>(nodes, g_wv, nullptr, gv, SN, DD, DD);
    sgemm_tc<0><<<dim3(2, 256), 256>>>(nodes, p_wk, nullptr, pk, SN, DD, DD);

    wct_kernel<<<256, 256>>>(g_wo, p_wq, wctb);
    bb_kernel<<<1, 256>>>(g_bo, p_wq, bbv);
    smallprec_kernel<<<1, 256>>>(g_wq, v1, v2, qgv2, qgfv1);

    sgemm_tc<0><<<dim3(2, 256), 256>>>(pk, wctb, nullptr, pkw, SN, DD, DD);
    pkb_kernel<<<SN / 8, 256>>>(pk, bbv, pkbb);

    sgemm_tc<0><<<dim3(2, 2), 256>>>(graphb, g_wq, nullptr, qggb, NB, DD, DD);
    sgemm_tc<0><<<dim3(2, 256), 256>>>(nodes, g_wq + 256 * 256, nullptr, qgp, SN, DD, DD);
    sgemm_tc<0><<<dim3(2, 256), 256>>>(nodes, g_wq + 512 * 256, nullptr, qgf, SN, DD, DD);

    // ---- full greedy decode in one kernel ----
    decode_kernel<<<NB, 256>>>(mask, gk, gv, pkw, qgp, qgf, qggb,
                               qgv2, qgfv1, pkbb, out);
}

// round 4
// speedup vs baseline: 2.1000x; 1.3477x over previous
#include <cuda_runtime.h>
#include <cuda_bf16.h>
#include <math.h>

// Problem constants
#define SS   128          // sequence length S
#define NB   256          // batch N
#define DD   256          // model dim D
#define NH   8            // heads
#define FFD  1024         // feed-forward dim
#define SN   (SS*NB)      // 32768 rows

// ---------------- scratch (device globals; no runtime allocation) ----------
__device__ float HBUF [SN*DD];        // h (S,N,D)
__device__ float QKVB [SN*3*DD];      // qkv; later: nodes(f32) | gk(bf16) | gv(bf16)
__device__ float BUF1 [SN*FFD];       // ff intermediate / attn out; later: pkW|qgp|qgf (bf16)
__device__ float BUF2 [SN*DD];        // proj/ff2 out; later: pk (f32)
__device__ float GRAPHB[NB*DD];
__device__ float QGGB [NB*DD];
__device__ float WCTB [DD*DD];        // (g_wo @ p_wq / 16)^T
__device__ float BBV  [DD];           // (g_bo @ p_wq)/16
__device__ float QGV2 [DD];           // v2 @ g_wq[256:512]
__device__ float QGFV1[DD];           // v1 @ g_wq[512:768]
__device__ float PKBB [SN];           // pk . BBV per (n,s)

// ---------------- simple copy ------------------------------------------------
__global__ void copy_f4(const float4* __restrict__ src, float4* __restrict__ dst, int n4) {
    int i = blockIdx.x * blockDim.x + threadIdx.x;
    if (i < n4) dst[i] = src[i];
}

// ---------------- helpers ----------------------------------------------------
__device__ __forceinline__ void mma_tf32(float* d, const unsigned* a, const unsigned* b) {
    asm volatile(
        "mma.sync.aligned.m16n8k8.row.col.f32.tf32.tf32.f32 "
        "{%0,%1,%2,%3},{%4,%5,%6,%7},{%8,%9},{%0,%1,%2,%3};"
        : "+f"(d[0]), "+f"(d[1]), "+f"(d[2]), "+f"(d[3])
        : "r"(a[0]), "r"(a[1]), "r"(a[2]), "r"(a[3]), "r"(b[0]), "r"(b[1]));
}
__device__ __forceinline__ void cp16(void* smem, const void* gmem) {
    unsigned s = (unsigned)__cvta_generic_to_shared(smem);
    asm volatile("cp.async.cg.shared.global [%0], [%1], 16;" :: "r"(s), "l"(gmem));
}
__device__ __forceinline__ void cp_commit() { asm volatile("cp.async.commit_group;"); }
template <int Nn>
__device__ __forceinline__ void cp_wait() { asm volatile("cp.async.wait_group %0;" :: "n"(Nn)); }

// dot of 8 bf16 (packed in uint4) with 8 floats
__device__ __forceinline__ float dot8bf(uint4 u, const float* __restrict__ q) {
    float2 a = __bfloat1622float2(*(__nv_bfloat162*)&u.x);
    float2 b = __bfloat1622float2(*(__nv_bfloat162*)&u.y);
    float2 c = __bfloat1622float2(*(__nv_bfloat162*)&u.z);
    float2 d = __bfloat1622float2(*(__nv_bfloat162*)&u.w);
    return a.x*q[0] + a.y*q[1] + b.x*q[2] + b.y*q[3]
         + c.x*q[4] + c.y*q[5] + d.x*q[6] + d.y*q[7];
}

// ---------------- tensor-core GEMM: C = A(MxK) @ B(KxNc) + bias --------------
// 128x128 tile, BK=16, 2-stage cp.async pipeline, 256 threads, tf32 mma.
// ACT: relu. OBF: write bf16 output.
template <int ACT, int OBF>
__global__ __launch_bounds__(256) void sgemm_tc(
    const float* __restrict__ A, const float* __restrict__ B,
    const float* __restrict__ bias, void* __restrict__ Cv,
    int M, int Nc, int K)
{
    __shared__ float As[2][128][20];
    __shared__ float Bs[2][16][136];
    int tid  = threadIdx.x;
    int lane = tid & 31, wid = tid >> 5;
    int wm = wid >> 2, wn = wid & 3;          // warp tile: (wm*64, wn*32)
    const float* Ab = A + (size_t)blockIdx.y * 128 * K;
    const float* Bb = B + blockIdx.x * 128;

    int ar_ld = tid >> 2,  ac_ld = (tid & 3) * 4;
    int br_ld = tid >> 5,  bc_ld = (tid & 31) * 4;

    float acc[4][4][4];
#pragma unroll
    for (int i = 0; i < 4; i++)
#pragma unroll
        for (int j = 0; j < 4; j++)
#pragma unroll
            for (int r = 0; r < 4; r++) acc[i][j][r] = 0.f;

    auto loadAB = [&](int k0, int st) {
#pragma unroll
        for (int i = 0; i < 2; i++) {
            int r = ar_ld + i * 64;
            cp16(&As[st][r][ac_ld], Ab + (size_t)r * K + k0 + ac_ld);
        }
#pragma unroll
        for (int i = 0; i < 2; i++) {
            int r = br_ld + i * 8;
            cp16(&Bs[st][r][bc_ld], Bb + (size_t)(k0 + r) * Nc + bc_ld);
        }
    };

    int nIt = K / 16;
    loadAB(0, 0);
    cp_commit();
    int buf = 0;

    for (int it = 0; it < nIt; it++) {
        if (it + 1 < nIt) loadAB((it + 1) * 16, buf ^ 1);
        cp_commit();
        cp_wait<1>();
        __syncthreads();

#pragma unroll
        for (int kk = 0; kk < 16; kk += 8) {
            unsigned afr[4][4], bfr[4][2];
            int ar = wm * 64 + (lane >> 2);
            int ac = kk + (lane & 3);
#pragma unroll
            for (int mt = 0; mt < 4; mt++) {
                afr[mt][0] = __float_as_uint(As[buf][ar + mt * 16    ][ac    ]);
                afr[mt][1] = __float_as_uint(As[buf][ar + mt * 16 + 8][ac    ]);
                afr[mt][2] = __float_as_uint(As[buf][ar + mt * 16    ][ac + 4]);
                afr[mt][3] = __float_as_uint(As[buf][ar + mt * 16 + 8][ac + 4]);
            }
            int bc = wn * 32 + (lane >> 2);
            int br = kk + (lane & 3);
#pragma unroll
            for (int nt = 0; nt < 4; nt++) {
                bfr[nt][0] = __float_as_uint(Bs[buf][br    ][bc + nt * 8]);
                bfr[nt][1] = __float_as_uint(Bs[buf][br + 4][bc + nt * 8]);
            }
#pragma unroll
            for (int mt = 0; mt < 4; mt++)
#pragma unroll
                for (int nt = 0; nt < 4; nt++)
                    mma_tf32(acc[mt][nt], afr[mt], bfr[nt]);
        }
        __syncthreads();
        buf ^= 1;
    }

    // epilogue
    int rbase = blockIdx.y * 128 + wm * 64 + (lane >> 2);
    int cbase = blockIdx.x * 128 + wn * 32 + 2 * (lane & 3);
#pragma unroll
    for (int nt = 0; nt < 4; nt++) {
        int col = cbase + nt * 8;
        float b0 = bias ? bias[col] : 0.f;
        float b1 = bias ? bias[col + 1] : 0.f;
#pragma unroll
        for (int mt = 0; mt < 4; mt++) {
            int row = rbase + mt * 16;
            float v0 = acc[mt][nt][0] + b0;
            float v1 = acc[mt][nt][1] + b1;
            float v2 = acc[mt][nt][2] + b0;
            float v3 = acc[mt][nt][3] + b1;
            if (ACT) {
                v0 = fmaxf(v0, 0.f); v1 = fmaxf(v1, 0.f);
                v2 = fmaxf(v2, 0.f); v3 = fmaxf(v3, 0.f);
            }
            if (OBF) {
                __nv_bfloat16* Cb = (__nv_bfloat16*)Cv;
                *(__nv_bfloat162*)(Cb + (size_t)row * Nc + col)       = __floats2bfloat162_rn(v0, v1);
                *(__nv_bfloat162*)(Cb + (size_t)(row + 8) * Nc + col) = __floats2bfloat162_rn(v2, v3);
            } else {
                float* C = (float*)Cv;
                *(float2*)(C + (size_t)row * Nc + col)       = make_float2(v0, v1);
                *(float2*)(C + (size_t)(row + 8) * Nc + col) = make_float2(v2, v3);
            }
        }
    }
}

// ---------------- encoder attention: one block per (n,h), flash-style --------
__global__ __launch_bounds__(128) void enc_attn_kernel(
    const float* __restrict__ qkv, const int* __restrict__ mask,
    float* __restrict__ outp)
{
    int n = blockIdx.x, h = blockIdx.y, q = threadIdx.x;
    __shared__ float Ks[128][32];
    __shared__ float Vs[128][32];
    __shared__ int   msk[128];

    const float* kr = qkv + ((size_t)q * NB + n) * 768 + 256 + h * 32;
#pragma unroll
    for (int i = 0; i < 8; i++) {
        *(float4*)&Ks[q][i * 4] = *(const float4*)(kr + i * 4);
        *(float4*)&Vs[q][i * 4] = *(const float4*)(kr + 256 + i * 4);
    }
    msk[q] = mask[n * SS + q];

    float qv[32];
    const float* qr = qkv + ((size_t)q * NB + n) * 768 + h * 32;
#pragma unroll
    for (int i = 0; i < 8; i++) *(float4*)&qv[i * 4] = *(const float4*)(qr + i * 4);
    __syncthreads();

    float m = -INFINITY, l = 0.f, acc[32];
#pragma unroll
    for (int j = 0; j < 32; j++) acc[j] = 0.f;

    for (int s = 0; s < 128; s++) {
        float sc;
        if (msk[s] == 0) sc = -1e9f;
        else {
            float d = 0.f;
#pragma unroll
            for (int j = 0; j < 32; j++) d += qv[j] * Ks[s][j];
            sc = d * 0.17677669529663687f;   // 1/sqrt(32)
        }
        float nm   = fmaxf(m, sc);
        float corr = expf(m - nm);
        float p    = expf(sc - nm);
        l = l * corr + p;
#pragma unroll
        for (int j = 0; j < 32; j++) acc[j] = acc[j] * corr + p * Vs[s][j];
        m = nm;
    }
    float inv = 1.f / l;
    float* op = outp + ((size_t)q * NB + n) * DD + h * 32;
#pragma unroll
    for (int j = 0; j < 32; j++) op[j] = acc[j] * inv;
}

// ---------------- residual + LayerNorm (in place into h) --------------------
__global__ __launch_bounds__(256) void ln_res_kernel(
    float* __restrict__ h, const float* __restrict__ r,
    const float* __restrict__ sg, const float* __restrict__ bg)
{
    int row = blockIdx.x, d = threadIdx.x;
    size_t off = (size_t)row * DD + d;
    float v = h[off] + r[off];
    __shared__ float red[8];

    float t = v;
#pragma unroll
    for (int o = 16; o; o >>= 1) t += __shfl_xor_sync(0xffffffffu, t, o);
    if ((d & 31) == 0) red[d >> 5] = t;
    __syncthreads();
    float mu = (red[0] + red[1] + red[2] + red[3] + red[4] + red[5] + red[6] + red[7]) * (1.f / DD);
    __syncthreads();

    float dv = v - mu;
    t = dv * dv;
#pragma unroll
    for (int o = 16; o; o >>= 1) t += __shfl_xor_sync(0xffffffffu, t, o);
    if ((d & 31) == 0) red[d >> 5] = t;
    __syncthreads();
    float var = (red[0] + red[1] + red[2] + red[3] + red[4] + red[5] + red[6] + red[7]) * (1.f / DD);

    h[off] = dv * rsqrtf(var + 1e-5f) * sg[d] + bg[d];
}

// ---------------- transpose h(S,N,D) -> nodes(N,S,D) ------------------------
__global__ void transpose_kernel(const float* __restrict__ h, float* __restrict__ nodes) {
    int b = blockIdx.x;                  // b = n*S + s
    int n = b >> 7, s = b & 127;
    int d = threadIdx.x;
    nodes[(size_t)b * DD + d] = h[((size_t)s * NB + n) * DD + d];
}

// ---------------- graph = mean over s of h ----------------------------------
__global__ void graph_kernel(const float* __restrict__ h, float* __restrict__ g) {
    int n = blockIdx.x, d = threadIdx.x;
    float acc = 0.f;
    for (int s = 0; s < SS; s++) acc += h[((size_t)s * NB + n) * DD + d];
    g[n * DD + d] = acc * (1.f / SS);
}

// ---------------- small precomputes -----------------------------------------
__global__ void wct_kernel(const float* __restrict__ g_wo, const float* __restrict__ p_wq,
                           float* __restrict__ wct) {
    int j = blockIdx.x, i = threadIdx.x;
    float acc = 0.f;
    for (int k = 0; k < 256; k++) acc += g_wo[i * 256 + k] * p_wq[k * 256 + j];
    wct[j * 256 + i] = acc * 0.0625f;
}
__global__ void bb_kernel(const float* __restrict__ g_bo, const float* __restrict__ p_wq,
                          float* __restrict__ bb) {
    int j = threadIdx.x;
    float acc = 0.f;
    for (int i = 0; i < 256; i++) acc += g_bo[i] * p_wq[i * 256 + j];
    bb[j] = acc * 0.0625f;
}
__global__ void smallprec_kernel(const float* __restrict__ g_wq,
                                 const float* __restrict__ v1, const float* __restrict__ v2,
                                 float* __restrict__ qgv2, float* __restrict__ qgfv1) {
    int j = threadIdx.x;
    float a = 0.f, b = 0.f;
    for (int k = 0; k < 256; k++) {
        a += v2[k] * g_wq[(256 + k) * 256 + j];
        b += v1[k] * g_wq[(512 + k) * 256 + j];
    }
    qgv2[j] = a;
    qgfv1[j] = b;
}
__global__ __launch_bounds__(256) void pkb_kernel(const float* __restrict__ pk,
                                                  const float* __restrict__ bb,
                                                  float* __restrict__ pkb) {
    int w = threadIdx.x >> 5, lane = threadIdx.x & 31;
    int row = blockIdx.x * 8 + w;
    const float* p = pk + (size_t)row * 256;
    float acc = 0.f;
#pragma unroll
    for (int k = 0; k < 8; k++) acc += p[lane + k * 32] * bb[lane + k * 32];
#pragma unroll
    for (int o = 16; o; o >>= 1) acc += __shfl_xor_sync(0xffffffffu, acc, o);
    if (!lane) pkb[row] = acc;
}

// ---------------- the whole 128-step greedy decode: 1 block per n -----------
// 512 threads. gk/gv/pkw/qgp/qgf are bf16. Masked rows' LOADS are skipped, but
// every warp-level shuffle is executed uniformly by all lanes (no divergence
// at __shfl_xor_sync).
__global__ __launch_bounds__(512) void decode_kernel(
    const int*   __restrict__ mask,
    const __nv_bfloat16* __restrict__ gk,  const __nv_bfloat16* __restrict__ gv,
    const __nv_bfloat16* __restrict__ pkw, const __nv_bfloat16* __restrict__ qgp,
    const __nv_bfloat16* __restrict__ qgf, const float* __restrict__ qgg,
    const float* __restrict__ qgv2, const float* __restrict__ qgfv1,
    const float* __restrict__ pkb, float* __restrict__ out)
{
    int n = blockIdx.x;
    int tid = threadIdx.x;
    __shared__ float qg[256], glp[256], qgPrev[256], qgFirst[256];
    __shared__ float glp_part[4][256];
    __shared__ float att[8][128];
    __shared__ float logits[128];
    __shared__ unsigned mbits[4];
    __shared__ int cur;

    if (tid < 256) { qgPrev[tid] = qgv2[tid]; qgFirst[tid] = qgfv1[tid]; }
    if (tid < 4) {
        unsigned b = 0;
        for (int j = 0; j < 32; j++)
            if (mask[n * SS + tid * 32 + j] == 0) b |= (1u << j);
        mbits[tid] = b;
    }
    float lps = 0.f;
    const float* qggn = qgg + n * 256;
    size_t nbase = (size_t)n * SS * DD;
    __syncthreads();

    for (int t = 0; t < SS; t++) {
        if (tid < 256) qg[tid] = qggn[tid] + qgPrev[tid] + qgFirst[tid];
        __syncthreads();

        // scores: 1024 (h,s) entries, 2 per thread; skip masked loads (no shfl here)
#pragma unroll
        for (int i = 0; i < 2; i++) {
            int idx = tid + i * 512;
            int h = idx >> 7, s = idx & 127;
            float v;
            if ((mbits[s >> 5] >> (s & 31)) & 1u) v = -1e9f;
            else {
                const uint4* g = (const uint4*)(gk + nbase + (size_t)s * DD + h * 32);
                float acc = 0.f;
#pragma unroll
                for (int j = 0; j < 4; j++) acc += dot8bf(g[j], qg + h * 32 + j * 8);
                v = acc * 0.17677669529663687f;
            }
            att[h][s] = v;
        }
        __syncthreads();

        // softmax per head: warps 0..7 (whole-warp uniform branch)
        {
            int w = tid >> 5, lane = tid & 31;
            if (w < 8) {
                float v0 = att[w][lane], v1 = att[w][lane + 32],
                      v2 = att[w][lane + 64], v3 = att[w][lane + 96];
                float m = fmaxf(fmaxf(v0, v1), fmaxf(v2, v3));
#pragma unroll
                for (int o = 16; o; o >>= 1) m = fmaxf(m, __shfl_xor_sync(0xffffffffu, m, o));
                float e0 = expf(v0 - m), e1 = expf(v1 - m), e2 = expf(v2 - m), e3 = expf(v3 - m);
                float s = e0 + e1 + e2 + e3;
#pragma unroll
                for (int o = 16; o; o >>= 1) s += __shfl_xor_sync(0xffffffffu, s, o);
                float inv = 1.f / s;
                att[w][lane]      = e0 * inv;
                att[w][lane + 32] = e1 * inv;
                att[w][lane + 64] = e2 * inv;
                att[w][lane + 96] = e3 * inv;
            }
        }
        __syncthreads();

        // glp partials: quarter = tid>>7 handles 32 s values, dp = tid&127 -> d pair
        // (no shfl here; per-s skip is safe)
        {
            int quarter = tid >> 7, dp = tid & 127;
            int d0 = dp * 2, h = dp >> 4;
            float ax = 0.f, ay = 0.f;
            int s0 = quarter * 32;
#pragma unroll 4
            for (int s = s0; s < s0 + 32; s++) {
                if ((mbits[s >> 5] >> (s & 31)) & 1u) continue;   // att==0 exactly
                float a = att[h][s];
                float2 vf = __bfloat1622float2(*(const __nv_bfloat162*)(gv + nbase + (size_t)s * DD + d0));
                ax += a * vf.x; ay += a * vf.y;
            }
            glp_part[quarter][d0] = ax;
            glp_part[quarter][d0 + 1] = ay;
        }
        __syncthreads();
        if (tid < 256)
            glp[tid] = glp_part[0][tid] + glp_part[1][tid] + glp_part[2][tid] + glp_part[3][tid];
        __syncthreads();

        // logits: 4 threads per s, 64 dims each. Loads skipped for masked s,
        // but shuffles executed by ALL lanes (uniform) to avoid divergence UB.
        {
            int s = tid >> 2, q = tid & 3;
            bool skip = (mbits[s >> 5] >> (s & 31)) & 1u;
            float acc = 0.f;
            if (!skip) {
                const uint4* p = (const uint4*)(pkw + nbase + (size_t)s * DD + q * 64);
#pragma unroll
                for (int j = 0; j < 8; j++) acc += dot8bf(p[j], glp + q * 64 + j * 8);
            }
            acc += __shfl_xor_sync(0xffffffffu, acc, 1);
            acc += __shfl_xor_sync(0xffffffffu, acc, 2);
            if (q == 0)
                logits[s] = skip ? -1e9f : 10.f * tanhf(acc + pkb[n * SS + s]);
        }
        __syncthreads();

        // argmax (first-max tie-break) + logsumexp in warp 0
        if (tid < 32) {
            float v[4];
#pragma unroll
            for (int k = 0; k < 4; k++) v[k] = logits[tid + k * 32];
            float bvv = v[0]; int bi = tid;
#pragma unroll
            for (int k = 1; k < 4; k++) {
                int s = tid + k * 32;
                if (v[k] > bvv) { bvv = v[k]; bi = s; }
            }
#pragma unroll
            for (int o = 16; o; o >>= 1) {
                float ov = __shfl_xor_sync(0xffffffffu, bvv, o);
                int   oi = __shfl_xor_sync(0xffffffffu, bi, o);
                if (ov > bvv || (ov == bvv && oi < bi)) { bvv = ov; bi = oi; }
            }
            float ssum = 0.f;
#pragma unroll
            for (int k = 0; k < 4; k++) ssum += expf(v[k] - bvv);
#pragma unroll
            for (int o = 16; o; o >>= 1) ssum += __shfl_xor_sync(0xffffffffu, ssum, o);
            if (tid == 0) { lps += -logf(ssum); cur = bi; }
        }
        __syncthreads();

        int ci = cur;
        if (tid < 256) {
            qgPrev[tid] = __bfloat162float(qgp[nbase + (size_t)ci * DD + tid]);
            if (t == 0) qgFirst[tid] = __bfloat162float(qgf[nbase + (size_t)ci * DD + tid]);
        }
        if (tid == 0) mbits[ci >> 5] |= (1u << (ci & 31));
        __syncthreads();
    }
    if (tid == 0) out[n] = lps;
}

// ---------------- driver ------------------------------------------------------
extern "C" void kernel_launch(void* const* d_in, const int* in_sizes, int n_in,
                              void* d_out, int out_size)
{
    (void)in_sizes; (void)n_in; (void)out_size;
    const float* x        = (const float*)d_in[0];
    const int*   mask     = (const int*)  d_in[1];
    const float* qkv_w    = (const float*)d_in[2];
    const float* qkv_b    = (const float*)d_in[3];
    const float* out_w    = (const float*)d_in[4];
    const float* out_b    = (const float*)d_in[5];
    const float* ff1_w    = (const float*)d_in[6];
    const float* ff1_b    = (const float*)d_in[7];
    const float* ff2_w    = (const float*)d_in[8];
    const float* ff2_b    = (const float*)d_in[9];
    const float* ln1_s    = (const float*)d_in[10];
    const float* ln1_b    = (const float*)d_in[11];
    const float* ln2_s    = (const float*)d_in[12];
    const float* ln2_b    = (const float*)d_in[13];
    const float* v1       = (const float*)d_in[14];
    const float* v2       = (const float*)d_in[15];
    const float* g_wq     = (const float*)d_in[16];
    const float* g_wk     = (const float*)d_in[17];
    const float* g_wv     = (const float*)d_in[18];
    const float* g_wo     = (const float*)d_in[19];
    const float* g_bo     = (const float*)d_in[20];
    const float* p_wq     = (const float*)d_in[21];
    const float* p_wk     = (const float*)d_in[22];
    float* out = (float*)d_out;

    float *hbuf, *qkvb, *buf1, *buf2, *graphb, *qggb, *wctb, *bbv, *qgv2, *qgfv1, *pkbb;
    cudaGetSymbolAddress((void**)&hbuf,  HBUF);
    cudaGetSymbolAddress((void**)&qkvb,  QKVB);
    cudaGetSymbolAddress((void**)&buf1,  BUF1);
    cudaGetSymbolAddress((void**)&buf2,  BUF2);
    cudaGetSymbolAddress((void**)&graphb,GRAPHB);
    cudaGetSymbolAddress((void**)&qggb,  QGGB);
    cudaGetSymbolAddress((void**)&wctb,  WCTB);
    cudaGetSymbolAddress((void**)&bbv,   BBV);
    cudaGetSymbolAddress((void**)&qgv2,  QGV2);
    cudaGetSymbolAddress((void**)&qgfv1, QGFV1);
    cudaGetSymbolAddress((void**)&pkbb,  PKBB);

    // h = x
    copy_f4<<<(SN * DD / 4 + 255) / 256, 256>>>((const float4*)x, (float4*)hbuf, SN * DD / 4);

    // ---- encoder: 3 layers ----
    for (int i = 0; i < 3; i++) {
        sgemm_tc<0,0><<<dim3(6, 256), 256>>>(hbuf, qkv_w + (size_t)i * DD * 3 * DD,
                                             qkv_b + i * 3 * DD, qkvb, SN, 768, DD);
        enc_attn_kernel<<<dim3(NB, NH), 128>>>(qkvb, mask, buf1);
        sgemm_tc<0,0><<<dim3(2, 256), 256>>>(buf1, out_w + (size_t)i * DD * DD,
                                             out_b + i * DD, buf2, SN, DD, DD);
        ln_res_kernel<<<SN, 256>>>(hbuf, buf2, ln1_s + i * DD, ln1_b + i * DD);
        sgemm_tc<1,0><<<dim3(8, 256), 256>>>(hbuf, ff1_w + (size_t)i * DD * FFD,
                                             ff1_b + i * FFD, buf1, SN, FFD, DD);
        sgemm_tc<0,0><<<dim3(2, 256), 256>>>(buf1, ff2_w + (size_t)i * FFD * DD,
                                             ff2_b + i * DD, buf2, SN, DD, FFD);
        ln_res_kernel<<<SN, 256>>>(hbuf, buf2, ln2_s + i * DD, ln2_b + i * DD);
    }

    // ---- decode precompute ----
    float* nodes = qkvb;                                       // (N,S,D) f32
    __nv_bfloat16* gk  = (__nv_bfloat16*)(qkvb + (size_t)SN * DD);
    __nv_bfloat16* gv  = (__nv_bfloat16*)(qkvb + (size_t)SN * DD + SN * DD / 2);
    __nv_bfloat16* pkw = (__nv_bfloat16*)buf1;
    __nv_bfloat16* qgp = (__nv_bfloat16*)(buf1 + (size_t)SN * DD / 2);
    __nv_bfloat16* qgf = (__nv_bfloat16*)(buf1 + (size_t)SN * DD);
    float* pk = buf2;

    transpose_kernel<<<SN, 256>>>(hbuf, nodes);
    graph_kernel<<<NB, 256>>>(hbuf, graphb);

    sgemm_tc<0,1><<<dim3(2, 256), 256>>>(nodes, g_wk, nullptr, gk, SN, DD, DD);
    sgemm_tc<0,1><<<dim3(2, 256), 256>>>(nodes, g_wv, nullptr, gv, SN, DD, DD);
    sgemm_tc<0,0><<<dim3(2, 256), 256>>>(nodes, p_wk, nullptr, pk, SN, DD, DD);

    wct_kernel<<<256, 256>>>(g_wo, p_wq, wctb);
    bb_kernel<<<1, 256>>>(g_bo, p_wq, bbv);
    smallprec_kernel<<<1, 256>>>(g_wq, v1, v2, qgv2, qgfv1);

    sgemm_tc<0,1><<<dim3(2, 256), 256>>>(pk, wctb, nullptr, pkw, SN, DD, DD);
    pkb_kernel<<<SN / 8, 256>>>(pk, bbv, pkbb);

    sgemm_tc<0,0><<<dim3(2, 2), 256>>>(graphb, g_wq, nullptr, qggb, NB, DD, DD);
    sgemm_tc<0,1><<<dim3(2, 256), 256>>>(nodes, g_wq + 256 * 256, nullptr, qgp, SN, DD, DD);
    sgemm_tc<0,1><<<dim3(2, 256), 256>>>(nodes, g_wq + 512 * 256, nullptr, qgf, SN, DD, DD);

    // ---- full greedy decode in one kernel ----
    decode_kernel<<<NB, 512>>>(mask, gk, gv, pkw, qgp, qgf, qggb,
                               qgv2, qgfv1, pkbb, out);
}

// round 5
// speedup vs baseline: 2.1952x; 1.0453x over previous
#include <cuda_runtime.h>
#include <cuda_bf16.h>
#include <math.h>

// Problem constants
#define SS   128          // sequence length S
#define NB   256          // batch N
#define DD   256          // model dim D
#define NH   8            // heads
#define FFD  1024         // feed-forward dim
#define SN   (SS*NB)      // 32768 rows

// ---------------- scratch (device globals; no runtime allocation) ----------
__device__ float HBUF [SN*DD];        // h (S,N,D)
__device__ float QKVB [SN*3*DD];      // qkv; later: nodes(f32) | gk(bf16) | gv(bf16)
__device__ float BUF1 [SN*FFD];       // ff intermediate / attn out; later: pkW|qgp|qgf (bf16)
__device__ float BUF2 [SN*DD];        // proj/ff2 out; later: pk (f32)
__device__ float GRAPHB[NB*DD];
__device__ float QGGB [NB*DD];
__device__ float WCTB [DD*DD];        // (g_wo @ p_wq / 16)^T
__device__ float BBV  [DD];           // (g_bo @ p_wq)/16
__device__ float QGV2 [DD];           // v2 @ g_wq[256:512]
__device__ float QGFV1[DD];           // v1 @ g_wq[512:768]
__device__ float PKBB [SN];           // pk . BBV per (n,s)

// ---------------- simple copy ------------------------------------------------
__global__ void copy_f4(const float4* __restrict__ src, float4* __restrict__ dst, int n4) {
    int i = blockIdx.x * blockDim.x + threadIdx.x;
    if (i < n4) dst[i] = src[i];
}

// ---------------- helpers ----------------------------------------------------
__device__ __forceinline__ void mma_tf32(float* d, const unsigned* a, const unsigned* b) {
    asm volatile(
        "mma.sync.aligned.m16n8k8.row.col.f32.tf32.tf32.f32 "
        "{%0,%1,%2,%3},{%4,%5,%6,%7},{%8,%9},{%0,%1,%2,%3};"
        : "+f"(d[0]), "+f"(d[1]), "+f"(d[2]), "+f"(d[3])
        : "r"(a[0]), "r"(a[1]), "r"(a[2]), "r"(a[3]), "r"(b[0]), "r"(b[1]));
}
__device__ __forceinline__ void cp16(void* smem, const void* gmem) {
    unsigned s = (unsigned)__cvta_generic_to_shared(smem);
    asm volatile("cp.async.cg.shared.global [%0], [%1], 16;" :: "r"(s), "l"(gmem));
}
__device__ __forceinline__ void cp_commit() { asm volatile("cp.async.commit_group;"); }
template <int Nn>
__device__ __forceinline__ void cp_wait() { asm volatile("cp.async.wait_group %0;" :: "n"(Nn)); }

// dot of 8 bf16 (packed in uint4) with 8 floats
__device__ __forceinline__ float dot8bf(uint4 u, const float* __restrict__ q) {
    float2 a = __bfloat1622float2(*(__nv_bfloat162*)&u.x);
    float2 b = __bfloat1622float2(*(__nv_bfloat162*)&u.y);
    float2 c = __bfloat1622float2(*(__nv_bfloat162*)&u.z);
    float2 d = __bfloat1622float2(*(__nv_bfloat162*)&u.w);
    return a.x*q[0] + a.y*q[1] + b.x*q[2] + b.y*q[3]
         + c.x*q[4] + c.y*q[5] + d.x*q[6] + d.y*q[7];
}

// ---------------- tensor-core GEMM: C = A(MxK) @ B(KxNc) + bias --------------
// 128x128 tile, BK=16, 2-stage cp.async pipeline, 256 threads, tf32 mma.
// ACT: relu. OBF: write bf16 output.
template <int ACT, int OBF>
__global__ __launch_bounds__(256) void sgemm_tc(
    const float* __restrict__ A, const float* __restrict__ B,
    const float* __restrict__ bias, void* __restrict__ Cv,
    int M, int Nc, int K)
{
    __shared__ float As[2][128][20];
    __shared__ float Bs[2][16][136];
    int tid  = threadIdx.x;
    int lane = tid & 31, wid = tid >> 5;
    int wm = wid >> 2, wn = wid & 3;          // warp tile: (wm*64, wn*32)
    const float* Ab = A + (size_t)blockIdx.y * 128 * K;
    const float* Bb = B + blockIdx.x * 128;

    int ar_ld = tid >> 2,  ac_ld = (tid & 3) * 4;
    int br_ld = tid >> 5,  bc_ld = (tid & 31) * 4;

    float acc[4][4][4];
#pragma unroll
    for (int i = 0; i < 4; i++)
#pragma unroll
        for (int j = 0; j < 4; j++)
#pragma unroll
            for (int r = 0; r < 4; r++) acc[i][j][r] = 0.f;

    auto loadAB = [&](int k0, int st) {
#pragma unroll
        for (int i = 0; i < 2; i++) {
            int r = ar_ld + i * 64;
            cp16(&As[st][r][ac_ld], Ab + (size_t)r * K + k0 + ac_ld);
        }
#pragma unroll
        for (int i = 0; i < 2; i++) {
            int r = br_ld + i * 8;
            cp16(&Bs[st][r][bc_ld], Bb + (size_t)(k0 + r) * Nc + bc_ld);
        }
    };

    int nIt = K / 16;
    loadAB(0, 0);
    cp_commit();
    int buf = 0;

    for (int it = 0; it < nIt; it++) {
        if (it + 1 < nIt) loadAB((it + 1) * 16, buf ^ 1);
        cp_commit();
        cp_wait<1>();
        __syncthreads();

#pragma unroll
        for (int kk = 0; kk < 16; kk += 8) {
            unsigned afr[4][4], bfr[4][2];
            int ar = wm * 64 + (lane >> 2);
            int ac = kk + (lane & 3);
#pragma unroll
            for (int mt = 0; mt < 4; mt++) {
                afr[mt][0] = __float_as_uint(As[buf][ar + mt * 16    ][ac    ]);
                afr[mt][1] = __float_as_uint(As[buf][ar + mt * 16 + 8][ac    ]);
                afr[mt][2] = __float_as_uint(As[buf][ar + mt * 16    ][ac + 4]);
                afr[mt][3] = __float_as_uint(As[buf][ar + mt * 16 + 8][ac + 4]);
            }
            int bc = wn * 32 + (lane >> 2);
            int br = kk + (lane & 3);
#pragma unroll
            for (int nt = 0; nt < 4; nt++) {
                bfr[nt][0] = __float_as_uint(Bs[buf][br    ][bc + nt * 8]);
                bfr[nt][1] = __float_as_uint(Bs[buf][br + 4][bc + nt * 8]);
            }
#pragma unroll
            for (int mt = 0; mt < 4; mt++)
#pragma unroll
                for (int nt = 0; nt < 4; nt++)
                    mma_tf32(acc[mt][nt], afr[mt], bfr[nt]);
        }
        __syncthreads();
        buf ^= 1;
    }

    // epilogue
    int rbase = blockIdx.y * 128 + wm * 64 + (lane >> 2);
    int cbase = blockIdx.x * 128 + wn * 32 + 2 * (lane & 3);
#pragma unroll
    for (int nt = 0; nt < 4; nt++) {
        int col = cbase + nt * 8;
        float b0 = bias ? bias[col] : 0.f;
        float b1 = bias ? bias[col + 1] : 0.f;
#pragma unroll
        for (int mt = 0; mt < 4; mt++) {
            int row = rbase + mt * 16;
            float v0 = acc[mt][nt][0] + b0;
            float v1 = acc[mt][nt][1] + b1;
            float v2 = acc[mt][nt][2] + b0;
            float v3 = acc[mt][nt][3] + b1;
            if (ACT) {
                v0 = fmaxf(v0, 0.f); v1 = fmaxf(v1, 0.f);
                v2 = fmaxf(v2, 0.f); v3 = fmaxf(v3, 0.f);
            }
            if (OBF) {
                __nv_bfloat16* Cb = (__nv_bfloat16*)Cv;
                *(__nv_bfloat162*)(Cb + (size_t)row * Nc + col)       = __floats2bfloat162_rn(v0, v1);
                *(__nv_bfloat162*)(Cb + (size_t)(row + 8) * Nc + col) = __floats2bfloat162_rn(v2, v3);
            } else {
                float* C = (float*)Cv;
                *(float2*)(C + (size_t)row * Nc + col)       = make_float2(v0, v1);
                *(float2*)(C + (size_t)(row + 8) * Nc + col) = make_float2(v2, v3);
            }
        }
    }
}

// ---------------- encoder attention: one block per (n,h), flash-style --------
__global__ __launch_bounds__(128) void enc_attn_kernel(
    const float* __restrict__ qkv, const int* __restrict__ mask,
    float* __restrict__ outp)
{
    int n = blockIdx.x, h = blockIdx.y, q = threadIdx.x;
    __shared__ float Ks[128][32];
    __shared__ float Vs[128][32];
    __shared__ int   msk[128];

    const float* kr = qkv + ((size_t)q * NB + n) * 768 + 256 + h * 32;
#pragma unroll
    for (int i = 0; i < 8; i++) {
        *(float4*)&Ks[q][i * 4] = *(const float4*)(kr + i * 4);
        *(float4*)&Vs[q][i * 4] = *(const float4*)(kr + 256 + i * 4);
    }
    msk[q] = mask[n * SS + q];

    float qv[32];
    const float* qr = qkv + ((size_t)q * NB + n) * 768 + h * 32;
#pragma unroll
    for (int i = 0; i < 8; i++) *(float4*)&qv[i * 4] = *(const float4*)(qr + i * 4);
    __syncthreads();

    float m = -INFINITY, l = 0.f, acc[32];
#pragma unroll
    for (int j = 0; j < 32; j++) acc[j] = 0.f;

    for (int s = 0; s < 128; s++) {
        float sc;
        if (msk[s] == 0) sc = -1e9f;
        else {
            float d = 0.f;
#pragma unroll
            for (int j = 0; j < 32; j++) d += qv[j] * Ks[s][j];
            sc = d * 0.17677669529663687f;   // 1/sqrt(32)
        }
        float nm   = fmaxf(m, sc);
        float corr = expf(m - nm);
        float p    = expf(sc - nm);
        l = l * corr + p;
#pragma unroll
        for (int j = 0; j < 32; j++) acc[j] = acc[j] * corr + p * Vs[s][j];
        m = nm;
    }
    float inv = 1.f / l;
    float* op = outp + ((size_t)q * NB + n) * DD + h * 32;
#pragma unroll
    for (int j = 0; j < 32; j++) op[j] = acc[j] * inv;
}

// ---------------- residual + LayerNorm (in place into h) --------------------
__global__ __launch_bounds__(256) void ln_res_kernel(
    float* __restrict__ h, const float* __restrict__ r,
    const float* __restrict__ sg, const float* __restrict__ bg)
{
    int row = blockIdx.x, d = threadIdx.x;
    size_t off = (size_t)row * DD + d;
    float v = h[off] + r[off];
    __shared__ float red[8];

    float t = v;
#pragma unroll
    for (int o = 16; o; o >>= 1) t += __shfl_xor_sync(0xffffffffu, t, o);
    if ((d & 31) == 0) red[d >> 5] = t;
    __syncthreads();
    float mu = (red[0] + red[1] + red[2] + red[3] + red[4] + red[5] + red[6] + red[7]) * (1.f / DD);
    __syncthreads();

    float dv = v - mu;
    t = dv * dv;
#pragma unroll
    for (int o = 16; o; o >>= 1) t += __shfl_xor_sync(0xffffffffu, t, o);
    if ((d & 31) == 0) red[d >> 5] = t;
    __syncthreads();
    float var = (red[0] + red[1] + red[2] + red[3] + red[4] + red[5] + red[6] + red[7]) * (1.f / DD);

    h[off] = dv * rsqrtf(var + 1e-5f) * sg[d] + bg[d];
}

// ---------------- transpose h(S,N,D) -> nodes(N,S,D) ------------------------
__global__ void transpose_kernel(const float* __restrict__ h, float* __restrict__ nodes) {
    int b = blockIdx.x;                  // b = n*S + s
    int n = b >> 7, s = b & 127;
    int d = threadIdx.x;
    nodes[(size_t)b * DD + d] = h[((size_t)s * NB + n) * DD + d];
}

// ---------------- graph = mean over s of h ----------------------------------
__global__ void graph_kernel(const float* __restrict__ h, float* __restrict__ g) {
    int n = blockIdx.x, d = threadIdx.x;
    float acc = 0.f;
    for (int s = 0; s < SS; s++) acc += h[((size_t)s * NB + n) * DD + d];
    g[n * DD + d] = acc * (1.f / SS);
}

// ---------------- small precomputes -----------------------------------------
__global__ void wct_kernel(const float* __restrict__ g_wo, const float* __restrict__ p_wq,
                           float* __restrict__ wct) {
    int j = blockIdx.x, i = threadIdx.x;
    float acc = 0.f;
    for (int k = 0; k < 256; k++) acc += g_wo[i * 256 + k] * p_wq[k * 256 + j];
    wct[j * 256 + i] = acc * 0.0625f;
}
__global__ void bb_kernel(const float* __restrict__ g_bo, const float* __restrict__ p_wq,
                          float* __restrict__ bb) {
    int j = threadIdx.x;
    float acc = 0.f;
    for (int i = 0; i < 256; i++) acc += g_bo[i] * p_wq[i * 256 + j];
    bb[j] = acc * 0.0625f;
}
__global__ void smallprec_kernel(const float* __restrict__ g_wq,
                                 const float* __restrict__ v1, const float* __restrict__ v2,
                                 float* __restrict__ qgv2, float* __restrict__ qgfv1) {
    int j = threadIdx.x;
    float a = 0.f, b = 0.f;
    for (int k = 0; k < 256; k++) {
        a += v2[k] * g_wq[(256 + k) * 256 + j];
        b += v1[k] * g_wq[(512 + k) * 256 + j];
    }
    qgv2[j] = a;
    qgfv1[j] = b;
}
__global__ __launch_bounds__(256) void pkb_kernel(const float* __restrict__ pk,
                                                  const float* __restrict__ bb,
                                                  float* __restrict__ pkb) {
    int w = threadIdx.x >> 5, lane = threadIdx.x & 31;
    int row = blockIdx.x * 8 + w;
    const float* p = pk + (size_t)row * 256;
    float acc = 0.f;
#pragma unroll
    for (int k = 0; k < 8; k++) acc += p[lane + k * 32] * bb[lane + k * 32];
#pragma unroll
    for (int o = 16; o; o >>= 1) acc += __shfl_xor_sync(0xffffffffu, acc, o);
    if (!lane) pkb[row] = acc;
}

// ---------------- full 128-step greedy decode, tables in SMEM ---------------
// 1 block per n, 512 threads. Dynamic smem holds gk|gv|pkw (192KB bf16).
// Row-per-warp access: lane j reads uint4 j of a 512B row -> conflict-free.
#define DEC_DYN_SMEM (3 * SS * DD * 2)     // 196608 bytes

__global__ __launch_bounds__(512) void decode_kernel(
    const int*   __restrict__ mask,
    const __nv_bfloat16* __restrict__ gk,  const __nv_bfloat16* __restrict__ gv,
    const __nv_bfloat16* __restrict__ pkw, const __nv_bfloat16* __restrict__ qgp,
    const __nv_bfloat16* __restrict__ qgf, const float* __restrict__ qgg,
    const float* __restrict__ qgv2, const float* __restrict__ qgfv1,
    const float* __restrict__ pkb, float* __restrict__ out)
{
    extern __shared__ __align__(16) unsigned char dynsmem[];
    __nv_bfloat16* sgk  = (__nv_bfloat16*)dynsmem;             // [128][256]
    __nv_bfloat16* sgv  = sgk + SS * DD;
    __nv_bfloat16* spkw = sgv + SS * DD;

    int n = blockIdx.x;
    int tid = threadIdx.x;
    int lane = tid & 31, w = tid >> 5;       // 16 warps
    __shared__ float qg[256], glp[256], qgPrev[256], qgFirst[256], qggs[256];
    __shared__ float glp_part[4][256];
    __shared__ float att[8][128];
    __shared__ float logits[128];
    __shared__ float spkb[128];
    __shared__ unsigned mbits[4];
    __shared__ int cur;

    size_t nbase = (size_t)n * SS * DD;

    // ---- stage tables into smem (12288 uint4 via cp.async) ----
    {
        uint4* d4 = (uint4*)dynsmem;
        const uint4* s_gk  = (const uint4*)(gk + nbase);
        const uint4* s_gv  = (const uint4*)(gv + nbase);
        const uint4* s_pkw = (const uint4*)(pkw + nbase);
#pragma unroll
        for (int i = 0; i < 8; i++) cp16(&d4[tid + i * 512],        &s_gk [tid + i * 512]);
#pragma unroll
        for (int i = 0; i < 8; i++) cp16(&d4[4096 + tid + i * 512], &s_gv [tid + i * 512]);
#pragma unroll
        for (int i = 0; i < 8; i++) cp16(&d4[8192 + tid + i * 512], &s_pkw[tid + i * 512]);
        cp_commit();
    }

    if (tid < 256) {
        qgPrev[tid]  = qgv2[tid];
        qgFirst[tid] = qgfv1[tid];
        qggs[tid]    = qgg[n * 256 + tid];
    }
    if (tid < 128) spkb[tid] = pkb[n * SS + tid];
    if (tid < 4) {
        unsigned b = 0;
        for (int j = 0; j < 32; j++)
            if (mask[n * SS + tid * 32 + j] == 0) b |= (1u << j);
        mbits[tid] = b;
    }
    float lps = 0.f;
    cp_wait<0>();
    __syncthreads();

    for (int t = 0; t < SS; t++) {
        if (tid < 256) qg[tid] = qggs[tid] + qgPrev[tid] + qgFirst[tid];
        __syncthreads();

        // ---- scores: warp w handles rows s = w, w+16, ...; lane j covers dims 8j..8j+7
        {
            float qreg[8];
#pragma unroll
            for (int k = 0; k < 8; k++) qreg[k] = qg[8 * lane + k];
            const uint4* gk4 = (const uint4*)sgk;
#pragma unroll
            for (int r = 0; r < 8; r++) {
                int s = w + r * 16;
                if ((mbits[s >> 5] >> (s & 31)) & 1u) {
                    if (lane < 8) att[lane][s] = -1e9f;
                } else {
                    float acc = dot8bf(gk4[s * 32 + lane], qreg);
                    acc += __shfl_xor_sync(0xffffffffu, acc, 1);
                    acc += __shfl_xor_sync(0xffffffffu, acc, 2);
                    if ((lane & 3) == 0) att[lane >> 2][s] = acc * 0.17677669529663687f;
                }
            }
        }
        __syncthreads();

        // ---- softmax per head: warps 0..7
        if (w < 8) {
            float v0 = att[w][lane], v1 = att[w][lane + 32],
                  v2 = att[w][lane + 64], v3 = att[w][lane + 96];
            float m = fmaxf(fmaxf(v0, v1), fmaxf(v2, v3));
#pragma unroll
            for (int o = 16; o; o >>= 1) m = fmaxf(m, __shfl_xor_sync(0xffffffffu, m, o));
            float e0 = expf(v0 - m), e1 = expf(v1 - m), e2 = expf(v2 - m), e3 = expf(v3 - m);
            float sm = e0 + e1 + e2 + e3;
#pragma unroll
            for (int o = 16; o; o >>= 1) sm += __shfl_xor_sync(0xffffffffu, sm, o);
            float inv = 1.f / sm;
            att[w][lane]      = e0 * inv;
            att[w][lane + 32] = e1 * inv;
            att[w][lane + 64] = e2 * inv;
            att[w][lane + 96] = e3 * inv;
        }
        __syncthreads();

        // ---- glp partials from smem gv: quarter (tid>>7) x 32 s-rows, dp -> d pair
        {
            int quarter = tid >> 7, dp = tid & 127;
            int d0 = dp * 2, h = dp >> 4;
            float ax = 0.f, ay = 0.f;
            int s0 = quarter * 32;
#pragma unroll 4
            for (int s = s0; s < s0 + 32; s++) {
                if ((mbits[s >> 5] >> (s & 31)) & 1u) continue;   // att==0 exactly
                float a = att[h][s];
                float2 vf = __bfloat1622float2(*(const __nv_bfloat162*)(sgv + s * DD + d0));
                ax += a * vf.x; ay += a * vf.y;
            }
            glp_part[quarter][d0] = ax;
            glp_part[quarter][d0 + 1] = ay;
        }
        __syncthreads();
        if (tid < 256)
            glp[tid] = glp_part[0][tid] + glp_part[1][tid] + glp_part[2][tid] + glp_part[3][tid];
        __syncthreads();

        // ---- logits: warp per row; lane j covers dims 8j..8j+7; full-warp reduce
        {
            float greg[8];
#pragma unroll
            for (int k = 0; k < 8; k++) greg[k] = glp[8 * lane + k];
            const uint4* pw4 = (const uint4*)spkw;
#pragma unroll
            for (int r = 0; r < 8; r++) {
                int s = w + r * 16;
                if ((mbits[s >> 5] >> (s & 31)) & 1u) {
                    if (lane == 0) logits[s] = -1e9f;
                } else {
                    float acc = dot8bf(pw4[s * 32 + lane], greg);
#pragma unroll
                    for (int o = 16; o; o >>= 1) acc += __shfl_xor_sync(0xffffffffu, acc, o);
                    if (lane == 0) logits[s] = 10.f * tanhf(acc + spkb[s]);
                }
            }
        }
        __syncthreads();

        // ---- argmax (first-max tie-break) + logsumexp in warp 0
        if (tid < 32) {
            float v[4];
#pragma unroll
            for (int k = 0; k < 4; k++) v[k] = logits[tid + k * 32];
            float bvv = v[0]; int bi = tid;
#pragma unroll
            for (int k = 1; k < 4; k++) {
                int s = tid + k * 32;
                if (v[k] > bvv) { bvv = v[k]; bi = s; }
            }
#pragma unroll
            for (int o = 16; o; o >>= 1) {
                float ov = __shfl_xor_sync(0xffffffffu, bvv, o);
                int   oi = __shfl_xor_sync(0xffffffffu, bi, o);
                if (ov > bvv || (ov == bvv && oi < bi)) { bvv = ov; bi = oi; }
            }
            float ssum = 0.f;
#pragma unroll
            for (int k = 0; k < 4; k++) ssum += expf(v[k] - bvv);
#pragma unroll
            for (int o = 16; o; o >>= 1) ssum += __shfl_xor_sync(0xffffffffu, ssum, o);
            if (tid == 0) { lps += -logf(ssum); cur = bi; }
        }
        __syncthreads();

        int ci = cur;
        if (tid < 256) {
            qgPrev[tid] = __bfloat162float(qgp[nbase + (size_t)ci * DD + tid]);
            if (t == 0) qgFirst[tid] = __bfloat162float(qgf[nbase + (size_t)ci * DD + tid]);
        }
        if (tid == 0) mbits[ci >> 5] |= (1u << (ci & 31));
        __syncthreads();
    }
    if (tid == 0) out[n] = lps;
}

// ---------------- driver ------------------------------------------------------
extern "C" void kernel_launch(void* const* d_in, const int* in_sizes, int n_in,
                              void* d_out, int out_size)
{
    (void)in_sizes; (void)n_in; (void)out_size;
    const float* x        = (const float*)d_in[0];
    const int*   mask     = (const int*)  d_in[1];
    const float* qkv_w    = (const float*)d_in[2];
    const float* qkv_b    = (const float*)d_in[3];
    const float* out_w    = (const float*)d_in[4];
    const float* out_b    = (const float*)d_in[5];
    const float* ff1_w    = (const float*)d_in[6];
    const float* ff1_b    = (const float*)d_in[7];
    const float* ff2_w    = (const float*)d_in[8];
    const float* ff2_b    = (const float*)d_in[9];
    const float* ln1_s    = (const float*)d_in[10];
    const float* ln1_b    = (const float*)d_in[11];
    const float* ln2_s    = (const float*)d_in[12];
    const float* ln2_b    = (const float*)d_in[13];
    const float* v1       = (const float*)d_in[14];
    const float* v2       = (const float*)d_in[15];
    const float* g_wq     = (const float*)d_in[16];
    const float* g_wk     = (const float*)d_in[17];
    const float* g_wv     = (const float*)d_in[18];
    const float* g_wo     = (const float*)d_in[19];
    const float* g_bo     = (const float*)d_in[20];
    const float* p_wq     = (const float*)d_in[21];
    const float* p_wk     = (const float*)d_in[22];
    float* out = (float*)d_out;

    float *hbuf, *qkvb, *buf1, *buf2, *graphb, *qggb, *wctb, *bbv, *qgv2, *qgfv1, *pkbb;
    cudaGetSymbolAddress((void**)&hbuf,  HBUF);
    cudaGetSymbolAddress((void**)&qkvb,  QKVB);
    cudaGetSymbolAddress((void**)&buf1,  BUF1);
    cudaGetSymbolAddress((void**)&buf2,  BUF2);
    cudaGetSymbolAddress((void**)&graphb,GRAPHB);
    cudaGetSymbolAddress((void**)&qggb,  QGGB);
    cudaGetSymbolAddress((void**)&wctb,  WCTB);
    cudaGetSymbolAddress((void**)&bbv,   BBV);
    cudaGetSymbolAddress((void**)&qgv2,  QGV2);
    cudaGetSymbolAddress((void**)&qgfv1, QGFV1);
    cudaGetSymbolAddress((void**)&pkbb,  PKBB);

    static bool attr_done = false;
    if (!attr_done) {
        cudaFuncSetAttribute(decode_kernel,
                             cudaFuncAttributeMaxDynamicSharedMemorySize, DEC_DYN_SMEM);
        attr_done = true;
    }

    // h = x
    copy_f4<<<(SN * DD / 4 + 255) / 256, 256>>>((const float4*)x, (float4*)hbuf, SN * DD / 4);

    // ---- encoder: 3 layers ----
    for (int i = 0; i < 3; i++) {
        sgemm_tc<0,0><<<dim3(6, 256), 256>>>(hbuf, qkv_w + (size_t)i * DD * 3 * DD,
                                             qkv_b + i * 3 * DD, qkvb, SN, 768, DD);
        enc_attn_kernel<<<dim3(NB, NH), 128>>>(qkvb, mask, buf1);
        sgemm_tc<0,0><<<dim3(2, 256), 256>>>(buf1, out_w + (size_t)i * DD * DD,
                                             out_b + i * DD, buf2, SN, DD, DD);
        ln_res_kernel<<<SN, 256>>>(hbuf, buf2, ln1_s + i * DD, ln1_b + i * DD);
        sgemm_tc<1,0><<<dim3(8, 256), 256>>>(hbuf, ff1_w + (size_t)i * DD * FFD,
                                             ff1_b + i * FFD, buf1, SN, FFD, DD);
        sgemm_tc<0,0><<<dim3(2, 256), 256>>>(buf1, ff2_w + (size_t)i * FFD * DD,
                                             ff2_b + i * DD, buf2, SN, DD, FFD);
        ln_res_kernel<<<SN, 256>>>(hbuf, buf2, ln2_s + i * DD, ln2_b + i * DD);
    }

    // ---- decode precompute ----
    float* nodes = qkvb;                                       // (N,S,D) f32
    __nv_bfloat16* gk  = (__nv_bfloat16*)(qkvb + (size_t)SN * DD);
    __nv_bfloat16* gv  = (__nv_bfloat16*)(qkvb + (size_t)SN * DD + SN * DD / 2);
    __nv_bfloat16* pkw = (__nv_bfloat16*)buf1;
    __nv_bfloat16* qgp = (__nv_bfloat16*)(buf1 + (size_t)SN * DD / 2);
    __nv_bfloat16* qgf = (__nv_bfloat16*)(buf1 + (size_t)SN * DD);
    float* pk = buf2;

    transpose_kernel<<<SN, 256>>>(hbuf, nodes);
    graph_kernel<<<NB, 256>>>(hbuf, graphb);

    sgemm_tc<0,1><<<dim3(2, 256), 256>>>(nodes, g_wk, nullptr, gk, SN, DD, DD);
    sgemm_tc<0,1><<<dim3(2, 256), 256>>>(nodes, g_wv, nullptr, gv, SN, DD, DD);
    sgemm_tc<0,0><<<dim3(2, 256), 256>>>(nodes, p_wk, nullptr, pk, SN, DD, DD);

    wct_kernel<<<256, 256>>>(g_wo, p_wq, wctb);
    bb_kernel<<<1, 256>>>(g_bo, p_wq, bbv);
    smallprec_kernel<<<1, 256>>>(g_wq, v1, v2, qgv2, qgfv1);

    sgemm_tc<0,1><<<dim3(2, 256), 256>>>(pk, wctb, nullptr, pkw, SN, DD, DD);
    pkb_kernel<<<SN / 8, 256>>>(pk, bbv, pkbb);

    sgemm_tc<0,0><<<dim3(2, 2), 256>>>(graphb, g_wq, nullptr, qggb, NB, DD, DD);
    sgemm_tc<0,1><<<dim3(2, 256), 256>>>(nodes, g_wq + 256 * 256, nullptr, qgp, SN, DD, DD);
    sgemm_tc<0,1><<<dim3(2, 256), 256>>>(nodes, g_wq + 512 * 256, nullptr, qgf, SN, DD, DD);

    // ---- full greedy decode in one kernel, tables resident in smem ----
    decode_kernel<<<NB, 512, DEC_DYN_SMEM>>>(mask, gk, gv, pkw, qgp, qgf, qggb,
                                             qgv2, qgfv1, pkbb, out);
}